// round 8
// baseline (speedup 1.0000x reference)
#include <cuda_runtime.h>
#include <cuda_bf16.h>
#include <cuda_fp16.h>
#include <math.h>
#include <stdint.h>

#define D_MODEL 2048
#define D_STATE 32
#define HEADDIM 128
#define NHEADS 16
#define D_CONVK 4
#define M_PREFIX 8
#define MAX_LOOPS 6
#define BRIDGE_RANK 64
#define VOCAB 50432
#define LORA_RANK 4
#define BSZ 2
#define TLEN 512
#define TE (M_PREFIX + TLEN)     /* 520 */
#define ROWS (BSZ * TE)          /* 1040 */
#define DIN (2*D_MODEL + 2*D_STATE + NHEADS)  /* 4176 */
#define CONV_CH (D_MODEL + 2*D_STATE)         /* 2112 */
#define OUTROWS (BSZ * TLEN)     /* 1024 */
#define NSEQ (BSZ * NHEADS)      /* 32 */
#define NCH 13
#define CHL 40                   /* NCH * CHL == TE */

// ---------------- scratch (static device globals; no allocs) ----------------
__device__ float g_xe[ROWS * D_MODEL];
__device__ float g_xp[OUTROWS * D_MODEL];
__device__ float g_zx[ROWS * DIN];
__device__ float g_xbc[ROWS * CONV_CH];
__device__ float g_dt[ROWS * NHEADS];
__device__ float g_dA[ROWS * NHEADS];
__device__ float g_y[ROWS * D_MODEL];
__device__ float g_mo[ROWS * D_MODEL];
__device__ float g_t1[ROWS * BRIDGE_RANK];
// chunked-scan state
__device__ float g_hs[(size_t)NSEQ * NCH * HEADDIM * D_STATE];
__device__ float g_pa[NSEQ * NCH];
__device__ float g_cum[NSEQ * TE];

// bf16 hi/lo operand buffers (Win GEMM)
__device__ __nv_bfloat16 g_WinH[DIN * D_MODEL],   g_WinL[DIN * D_MODEL];
__device__ __nv_bfloat16 g_actH[ROWS * D_MODEL],  g_actL[ROWS * D_MODEL];
// fp16 operand buffers (Wout GEMM + logits GEMM, single-pass)
__device__ __half g_WoutF[D_MODEL * D_MODEL];
__device__ __half g_actF[ROWS * D_MODEL];
__device__ __half g_embF[(size_t)VOCAB * D_MODEL];
__device__ __half g_finF[OUTROWS * D_MODEL];

__device__ __forceinline__ float siluf(float x) { return x / (1.0f + expf(-x)); }

__device__ __forceinline__ uint32_t smem_u32(const void* p) {
    uint32_t a;
    asm("{ .reg .u64 t; cvta.to.shared.u64 t, %1; cvt.u32.u64 %0, t; }" : "=r"(a) : "l"(p));
    return a;
}
__device__ __forceinline__ void cpa16(uint32_t dst, const void* src, uint32_t bytes) {
    asm volatile("cp.async.cg.shared.global [%0], [%1], 16, %2;" :: "r"(dst), "l"(src), "r"(bytes));
}
__device__ __forceinline__ void split1(float v, __nv_bfloat16* hi, __nv_bfloat16* lo, size_t i) {
    __nv_bfloat16 h = __float2bfloat16(v);
    hi[i] = h;
    lo[i] = __float2bfloat16(v - __bfloat162float(h));
}

// ================= shared GEMM tile constants =================
#define KC 32
#define SROW 40
/* per-array bytes: rows * SROW * 2 */
#define AB64  (64 * SROW * 2)       /* 5120  */
#define AB128 (128 * SROW * 2)      /* 10240 */
#define STG_BF64  (2*AB64 + 2*AB128)   /* 30720 : AH AL BH BL */
#define STG_F64   (AB64 + AB128)       /* 15360 : A B */
#define STG_F128  (2*AB128)            /* 20480 : A B */

#define LDSM4(r, addr) \
    asm volatile("ldmatrix.sync.aligned.m8n8.x4.shared.b16 {%0,%1,%2,%3}, [%4];" \
        : "=r"((r)[0]), "=r"((r)[1]), "=r"((r)[2]), "=r"((r)[3]) : "r"(addr))

#define MMA_BF(d, a, b0, b1) \
    asm volatile("mma.sync.aligned.m16n8k16.row.col.f32.bf16.bf16.f32 " \
        "{%0,%1,%2,%3},{%4,%5,%6,%7},{%8,%9},{%0,%1,%2,%3};" \
        : "+f"((d)[0]), "+f"((d)[1]), "+f"((d)[2]), "+f"((d)[3]) \
        : "r"((a)[0]), "r"((a)[1]), "r"((a)[2]), "r"((a)[3]), "r"(b0), "r"(b1))

#define MMA_F16(d, a, b0, b1) \
    asm volatile("mma.sync.aligned.m16n8k16.row.col.f32.f16.f16.f32 " \
        "{%0,%1,%2,%3},{%4,%5,%6,%7},{%8,%9},{%0,%1,%2,%3};" \
        : "+f"((d)[0]), "+f"((d)[1]), "+f"((d)[2]), "+f"((d)[3]) \
        : "r"((a)[0]), "r"((a)[1]), "r"((a)[2]), "r"((a)[3]), "r"(b0), "r"(b1))

// ---- generic epilogue (TM = 32*MT*2 rows per CTA, warp grid 2xM 4xN) ----
template<int MT>
__device__ __forceinline__ void epi_store(float acc[MT][4][4], float* C,
        int m0, int n0, int M, int N, int wm, int wn, int lane) {
#pragma unroll
    for (int mt = 0; mt < MT; mt++) {
#pragma unroll
        for (int nt = 0; nt < 4; nt++) {
            int m = m0 + wm * (MT * 16) + mt * 16 + (lane >> 2);
            int n = n0 + wn * 32 + nt * 8 + (lane & 3) * 2;
            if (n < N) {
                if (m < M) {
                    float2 v = make_float2(acc[mt][nt][0], acc[mt][nt][1]);
                    *(float2*)(C + (size_t)m * N + n) = v;
                }
                if (m + 8 < M) {
                    float2 v = make_float2(acc[mt][nt][2], acc[mt][nt][3]);
                    *(float2*)(C + (size_t)(m + 8) * N + n) = v;
                }
            }
        }
    }
}

// ================= bf16x3 GEMM, TM=64 (Win): C = A @ B^T =================
__device__ __forceinline__ void load_bf64(uint32_t sbase,
        const __nv_bfloat16* AH, const __nv_bfloat16* AL,
        const __nv_bfloat16* BH, const __nv_bfloat16* BL,
        int m0, int n0, int k0, int M, int N, int K, int tid) {
    // chunks: AH [0,256) AL [256,512) BH [512,1024) BL [1024,1536)
#pragma unroll
    for (int i = 0; i < 6; i++) {
        int idx = tid + (i << 8);
        const __nv_bfloat16* base;
        uint32_t arroff;
        int row, col, g, lim;
        if (idx < 512) {
            base = (idx < 256) ? AH : AL;
            arroff = (idx < 256) ? 0u : (uint32_t)AB64;
            int c = idx & 255;
            row = c >> 2; col = c & 3;
            g = m0 + row; lim = M;
        } else {
            base = (idx < 1024) ? BH : BL;
            arroff = (idx < 1024) ? (uint32_t)(2*AB64) : (uint32_t)(2*AB64 + AB128);
            int c = (idx - 512) & 511;
            row = c >> 2; col = c & 3;
            g = n0 + row; lim = N;
        }
        uint32_t bytes = 16;
        if (g >= lim) { g = 0; bytes = 0; }
        cpa16(sbase + arroff + (uint32_t)(row * 80 + col * 16),
              base + (size_t)g * K + k0 + col * 8, bytes);
    }
}

__global__ void __launch_bounds__(256, 3) gemm_bf3_64(
        const __nv_bfloat16* __restrict__ AH, const __nv_bfloat16* __restrict__ AL,
        const __nv_bfloat16* __restrict__ BH, const __nv_bfloat16* __restrict__ BL,
        float* __restrict__ C, int M, int N, int K) {
    extern __shared__ __align__(16) char smdyn[];
    uint32_t sb = smem_u32(smdyn);

    int tid = threadIdx.x, lane = tid & 31, wid = tid >> 5;
    int wm = wid >> 2, wn = wid & 3;       // 2 x 4 warp grid, warp tile 32x32
    int m0 = blockIdx.x * 64, n0 = blockIdx.y * 128;

    float acc[2][4][4] = {};

    uint32_t aRow = (uint32_t)(wm * 32 + (lane & 15));
    uint32_t aColB = (uint32_t)((lane >> 4) * 8) * 2;
    uint32_t bRow = (uint32_t)(wn * 32 + ((lane >> 4) & 1) * 8 + (lane & 7));
    uint32_t bColB = (uint32_t)(((lane >> 3) & 1) * 8) * 2;

    const int nch = K >> 5;
    load_bf64(sb, AH, AL, BH, BL, m0, n0, 0, M, N, K, tid);
    asm volatile("cp.async.commit_group;" ::: "memory");
    for (int ch = 0; ch < nch; ch++) {
        asm volatile("cp.async.wait_group 0;" ::: "memory");
        __syncthreads();
        uint32_t uS = sb + (uint32_t)((ch & 1) * STG_BF64);
        if (ch + 1 < nch)
            load_bf64(sb + (uint32_t)(((ch + 1) & 1) * STG_BF64), AH, AL, BH, BL,
                      m0, n0, (ch + 1) * KC, M, N, K, tid);
        asm volatile("cp.async.commit_group;" ::: "memory");
        uint32_t uAH = uS, uAL = uS + AB64, uBH = uS + 2*AB64, uBL = uS + 2*AB64 + AB128;
#pragma unroll
        for (int ks = 0; ks < 2; ks++) {
            uint32_t kcb = (uint32_t)(ks * 16) * 2;
            uint32_t a[2][4], b[2][4];
            // pass 1: Ah * Bh
#pragma unroll
            for (int mt = 0; mt < 2; mt++)
                LDSM4(a[mt], uAH + ((aRow + mt * 16) * SROW) * 2 + kcb + aColB);
#pragma unroll
            for (int bt = 0; bt < 2; bt++)
                LDSM4(b[bt], uBH + ((bRow + bt * 16) * SROW) * 2 + kcb + bColB);
#pragma unroll
            for (int mt = 0; mt < 2; mt++)
#pragma unroll
                for (int nt = 0; nt < 4; nt++)
                    MMA_BF(acc[mt][nt], a[mt], b[nt >> 1][(nt & 1) * 2], b[nt >> 1][(nt & 1) * 2 + 1]);
            // pass 2: Al * Bh (reuse b)
#pragma unroll
            for (int mt = 0; mt < 2; mt++)
                LDSM4(a[mt], uAL + ((aRow + mt * 16) * SROW) * 2 + kcb + aColB);
#pragma unroll
            for (int mt = 0; mt < 2; mt++)
#pragma unroll
                for (int nt = 0; nt < 4; nt++)
                    MMA_BF(acc[mt][nt], a[mt], b[nt >> 1][(nt & 1) * 2], b[nt >> 1][(nt & 1) * 2 + 1]);
            // pass 3: Ah * Bl (reload a=H, b=L)
#pragma unroll
            for (int mt = 0; mt < 2; mt++)
                LDSM4(a[mt], uAH + ((aRow + mt * 16) * SROW) * 2 + kcb + aColB);
#pragma unroll
            for (int bt = 0; bt < 2; bt++)
                LDSM4(b[bt], uBL + ((bRow + bt * 16) * SROW) * 2 + kcb + bColB);
#pragma unroll
            for (int mt = 0; mt < 2; mt++)
#pragma unroll
                for (int nt = 0; nt < 4; nt++)
                    MMA_BF(acc[mt][nt], a[mt], b[nt >> 1][(nt & 1) * 2], b[nt >> 1][(nt & 1) * 2 + 1]);
        }
    }
    epi_store<2>(acc, C, m0, n0, M, N, wm, wn, lane);
}

// ================= fp16 single-pass GEMM, templated TM (Wout 64, logits 128) =================
template<int TM>
__device__ __forceinline__ void load_f16t(uint32_t sbase,
        const __half* A, const __half* B,
        int m0, int n0, int k0, int M, int N, int K, int tid) {
    const int ACH = TM * 4;                 // A chunks
    const int TOT = ACH + 512;              // + B chunks (128 rows)
#pragma unroll
    for (int i = 0; i < TOT / 256; i++) {
        int idx = tid + (i << 8);
        const __half* base;
        uint32_t arroff;
        int row, col, g, lim;
        if (idx < ACH) {
            base = A; arroff = 0;
            row = idx >> 2; col = idx & 3;
            g = m0 + row; lim = M;
        } else {
            base = B; arroff = (uint32_t)(TM * 80);
            int c = idx - ACH;
            row = c >> 2; col = c & 3;
            g = n0 + row; lim = N;
        }
        uint32_t bytes = 16;
        if (g >= lim) { g = 0; bytes = 0; }
        cpa16(sbase + arroff + (uint32_t)(row * 80 + col * 16),
              base + (size_t)g * K + k0 + col * 8, bytes);
    }
}

template<int TM, int MINB>
__global__ void __launch_bounds__(256, MINB) gemm_f16_t(
        const __half* __restrict__ A, const __half* __restrict__ B,
        float* __restrict__ C, int M, int N, int K) {
    extern __shared__ __align__(16) char smdyn[];
    uint32_t sb = smem_u32(smdyn);
    const int MT = TM / 32;
    const int STG = TM * 80 + AB128;

    int tid = threadIdx.x, lane = tid & 31, wid = tid >> 5;
    int wm = wid >> 2, wn = wid & 3;
    int m0 = blockIdx.x * TM, n0 = blockIdx.y * 128;

    float acc[MT][4][4] = {};

    uint32_t aRow = (uint32_t)(wm * (MT * 16) + (lane & 15));
    uint32_t aColB = (uint32_t)((lane >> 4) * 8) * 2;
    uint32_t bRow = (uint32_t)(wn * 32 + ((lane >> 4) & 1) * 8 + (lane & 7));
    uint32_t bColB = (uint32_t)(((lane >> 3) & 1) * 8) * 2;

    const int nch = K >> 5;
    load_f16t<TM>(sb, A, B, m0, n0, 0, M, N, K, tid);
    asm volatile("cp.async.commit_group;" ::: "memory");
    for (int ch = 0; ch < nch; ch++) {
        asm volatile("cp.async.wait_group 0;" ::: "memory");
        __syncthreads();
        uint32_t uS = sb + (uint32_t)((ch & 1) * STG);
        if (ch + 1 < nch)
            load_f16t<TM>(sb + (uint32_t)(((ch + 1) & 1) * STG), A, B,
                          m0, n0, (ch + 1) * KC, M, N, K, tid);
        asm volatile("cp.async.commit_group;" ::: "memory");
        uint32_t uA = uS, uB = uS + (uint32_t)(TM * 80);
#pragma unroll
        for (int ks = 0; ks < 2; ks++) {
            uint32_t kcb = (uint32_t)(ks * 16) * 2;
            uint32_t a[MT][4], b[2][4];
#pragma unroll
            for (int mt = 0; mt < MT; mt++)
                LDSM4(a[mt], uA + ((aRow + mt * 16) * SROW) * 2 + kcb + aColB);
#pragma unroll
            for (int bt = 0; bt < 2; bt++)
                LDSM4(b[bt], uB + ((bRow + bt * 16) * SROW) * 2 + kcb + bColB);
#pragma unroll
            for (int mt = 0; mt < MT; mt++)
#pragma unroll
                for (int nt = 0; nt < 4; nt++)
                    MMA_F16(acc[mt][nt], a[mt], b[nt >> 1][(nt & 1) * 2], b[nt >> 1][(nt & 1) * 2 + 1]);
        }
    }
    epi_store<MT>(acc, C, m0, n0, M, N, wm, wn, lane);
}

// ---------------- fused LoRA fold: Win -> bf16 hi/lo, Wout -> fp16 ----------------
__global__ void k_lora2(const float* __restrict__ in_base, const float* __restrict__ in_A,
                        const float* __restrict__ in_B,
                        const float* __restrict__ out_base, const float* __restrict__ out_A,
                        const float* __restrict__ out_B) {
    int i = blockIdx.x * 256 + threadIdx.x;
    const int T1 = DIN * D_MODEL;
    if (i < T1) {
        int r = i / D_MODEL, c = i % D_MODEL;
        float s = 0.f;
#pragma unroll
        for (int q = 0; q < LORA_RANK; q++) s += in_B[r*LORA_RANK + q] * in_A[q*D_MODEL + c];
        split1(in_base[i] + 2.0f * s, g_WinH, g_WinL, i);
    } else {
        int j = i - T1;
        if (j >= D_MODEL * D_MODEL) return;
        int r = j / D_MODEL, c = j % D_MODEL;
        float s = 0.f;
#pragma unroll
        for (int q = 0; q < LORA_RANK; q++) s += out_B[r*LORA_RANK + q] * out_A[q*D_MODEL + c];
        g_WoutF[j] = __float2half(out_base[j] + 2.0f * s);
    }
}

// ---------------- f32 -> fp16 convert (vectorized), for emb ----------------
__global__ void k_cvt_f16(const float* __restrict__ in, __half* __restrict__ o, size_t n4) {
    size_t i = (size_t)blockIdx.x * 256 + threadIdx.x;
    if (i >= n4) return;
    float4 v = *(const float4*)(in + i * 4);
    __half2 p0 = __floats2half2_rn(v.x, v.y);
    __half2 p1 = __floats2half2_rn(v.z, v.w);
    uint2 pk;
    pk.x = *(uint32_t*)&p0;
    pk.y = *(uint32_t*)&p1;
    *(uint2*)(o + i * 4) = pk;
}

// ---------------- embedding gather + latent prefix ----------------
__global__ void k_embed(const int* __restrict__ ids, const float* __restrict__ emb,
                        const float* __restrict__ latent) {
    int i = blockIdx.x * 256 + threadIdx.x;
    if (i >= ROWS * D_MODEL) return;
    int row = i / D_MODEL, c = i % D_MODEL;
    int b = row / TE, t = row % TE;
    float v;
    if (t < M_PREFIX) {
        v = latent[t * D_MODEL + c];
    } else {
        int tok = ids[b * TLEN + (t - M_PREFIX)];
        v = emb[(size_t)tok * D_MODEL + c];
        g_xp[(b * TLEN + (t - M_PREFIX)) * D_MODEL + c] = v;
    }
    g_xe[i] = v;
}

// ---------------- lifeline + RoPE (loop start); emits f32 residual + bf16 hi/lo ----------------
__global__ void k_prerope(const float* __restrict__ gate, float loop_i) {
    int row = blockIdx.x;
    int j = threadIdx.x;              // pair index 0..1023
    int b = row / TE, t = row % TE;
    float v0 = g_xe[row * D_MODEL + 2*j];
    float v1 = g_xe[row * D_MODEL + 2*j + 1];
    if (t >= M_PREFIX) {
        int pr = (b * TLEN + t - M_PREFIX) * D_MODEL;
        v0 += gate[2*j]     * g_xp[pr + 2*j];
        v1 += gate[2*j + 1] * g_xp[pr + 2*j + 1];
    }
    float freq = loop_i * powf(10000.0f, -(float)(2*j) / (float)D_MODEL);
    float s, c;
    sincosf(freq, &s, &c);
    float r0 = v0 * c - v1 * s;
    float r1 = v1 * c + v0 * s;
    size_t o = (size_t)row * D_MODEL + 2*j;
    g_xe[o] = r0; g_xe[o + 1] = r1;
    split1(r0, g_actH, g_actL, o);
    split1(r1, g_actH, g_actL, o + 1);
}

// ---------------- fused: xe = rmsnorm(xe + mo) -> lifeline -> rope(next loop) ----------------
__global__ void k_addnorm_rope(const float* __restrict__ w, const float* __restrict__ gate,
                               float loop_i) {
    int row = blockIdx.x;
    int b = row / TE, t = row % TE;
    float v[4][2];
    float ss = 0.f;
#pragma unroll
    for (int q = 0; q < 4; q++) {
        int j = threadIdx.x + q * 256;       // pair index
        size_t o = (size_t)row * D_MODEL + 2*j;
        float a0 = g_xe[o]     + g_mo[o];
        float a1 = g_xe[o + 1] + g_mo[o + 1];
        v[q][0] = a0; v[q][1] = a1;
        ss += a0 * a0 + a1 * a1;
    }
    __shared__ float sred[8];
    for (int o = 16; o > 0; o >>= 1) ss += __shfl_down_sync(0xffffffffu, ss, o);
    if ((threadIdx.x & 31) == 0) sred[threadIdx.x >> 5] = ss;
    __syncthreads();
    if (threadIdx.x < 8) {
        float tt = sred[threadIdx.x];
        tt += __shfl_down_sync(0xffu, tt, 4);
        tt += __shfl_down_sync(0xffu, tt, 2);
        tt += __shfl_down_sync(0xffu, tt, 1);
        if (threadIdx.x == 0) sred[0] = tt;
    }
    __syncthreads();
    float scale = rsqrtf(sred[0] / (float)D_MODEL + 1e-6f);
#pragma unroll
    for (int q = 0; q < 4; q++) {
        int j = threadIdx.x + q * 256;
        size_t o = (size_t)row * D_MODEL + 2*j;
        float r0 = v[q][0] * scale * w[2*j];
        float r1 = v[q][1] * scale * w[2*j + 1];
        if (t >= M_PREFIX) {
            size_t pr = (size_t)(b * TLEN + t - M_PREFIX) * D_MODEL;
            r0 += gate[2*j]     * g_xp[pr + 2*j];
            r1 += gate[2*j + 1] * g_xp[pr + 2*j + 1];
        }
        float freq = loop_i * powf(10000.0f, -(float)(2*j) / (float)D_MODEL);
        float s, c;
        sincosf(freq, &s, &c);
        float o0 = r0 * c - r1 * s;
        float o1 = r1 * c + r0 * s;
        g_xe[o] = o0; g_xe[o + 1] = o1;
        split1(o0, g_actH, g_actL, o);
        split1(o1, g_actH, g_actL, o + 1);
    }
}

// ---------------- conv (K=4) + bias + silu, fused with dt/dA ----------------
__global__ void k_conv(const float* __restrict__ cw, const float* __restrict__ cb,
                       const float* __restrict__ dt_bias, const float* __restrict__ A_log) {
    int i = blockIdx.x * 256 + threadIdx.x;
    if (i < ROWS * NHEADS) {
        int row = i / NHEADS, h = i % NHEADS;
        float x = g_zx[(size_t)row * DIN + (2*D_MODEL + 2*D_STATE) + h] + dt_bias[h];
        float sp = (x > 20.f) ? x : log1pf(expf(x));
        g_dt[i] = sp;
        g_dA[i] = expf(-expf(A_log[h]) * sp);
    }
    if (i >= ROWS * CONV_CH) return;
    int row = i / CONV_CH, c = i % CONV_CH;
    int b = row / TE, t = row % TE;
    float acc = cb[c];
#pragma unroll
    for (int k = 0; k < D_CONVK; k++) {
        int tt = t - (D_CONVK - 1) + k;
        if (tt >= 0) acc += g_zx[((size_t)(b*TE + tt)) * DIN + D_MODEL + c] * cw[c*D_CONVK + k];
    }
    g_xbc[i] = siluf(acc);
}

// ---------------- chunked scan phase 1: local scan per (seq, chunk) ----------------
__global__ void k_scan_local(const float* __restrict__ D_skip) {
    int sc = blockIdx.x;               // seq * NCH + c
    int seq = sc / NCH, c = sc % NCH;
    int b = seq >> 4, h = seq & 15;
    int p = threadIdx.x;
    int t0 = c * CHL;
    float hs[D_STATE];
#pragma unroll
    for (int n = 0; n < D_STATE; n++) hs[n] = 0.f;
    __shared__ float sB[2][D_STATE], sC[2][D_STATE];
    float Dh = D_skip[h];
    float cum = 1.f;

    const float* row0 = g_xbc + (size_t)(b*TE + t0) * CONV_CH;
    if (p < 2*D_STATE) {
        float v = row0[D_MODEL + p];
        if (p < D_STATE) sB[0][p] = v; else sC[0][p - D_STATE] = v;
    }
    float x   = row0[h * HEADDIM + p];
    float dAv = g_dA[(size_t)(b*TE + t0) * NHEADS + h];
    float dtv = g_dt[(size_t)(b*TE + t0) * NHEADS + h];
    __syncthreads();

    for (int tt = 0; tt < CHL; tt++) {
        int t = t0 + tt;
        int tn = (tt + 1 < CHL) ? t + 1 : t;
        size_t rn = (size_t)(b*TE + tn);
        const float* rown = g_xbc + rn * CONV_CH;
        float xn   = rown[h * HEADDIM + p];
        float dAn  = g_dA[rn * NHEADS + h];
        float dtn  = g_dt[rn * NHEADS + h];
        int nxt = (tt + 1) & 1, cur = tt & 1;
        if (p < 2*D_STATE) {
            float v = rown[D_MODEL + p];
            if (p < D_STATE) sB[nxt][p] = v; else sC[nxt][p - D_STATE] = v;
        }
        cum *= dAv;
        float coef = dtv * x;
        float a0 = 0.f, a1 = 0.f, a2 = 0.f, a3 = 0.f;
#pragma unroll
        for (int n = 0; n < D_STATE; n += 4) {
            hs[n+0] = dAv * hs[n+0] + coef * sB[cur][n+0]; a0 += hs[n+0] * sC[cur][n+0];
            hs[n+1] = dAv * hs[n+1] + coef * sB[cur][n+1]; a1 += hs[n+1] * sC[cur][n+1];
            hs[n+2] = dAv * hs[n+2] + coef * sB[cur][n+2]; a2 += hs[n+2] * sC[cur][n+2];
            hs[n+3] = dAv * hs[n+3] + coef * sB[cur][n+3]; a3 += hs[n+3] * sC[cur][n+3];
        }
        g_y[(size_t)(b*TE + t) * D_MODEL + h * HEADDIM + p] = (a0 + a1) + (a2 + a3) + Dh * x;
        if (p == 0) g_cum[seq * TE + t] = cum;
        __syncthreads();
        x = xn; dAv = dAn; dtv = dtn;
    }
    size_t hbase = (size_t)sc * (HEADDIM * D_STATE) + (size_t)p * D_STATE;
#pragma unroll
    for (int n = 0; n < D_STATE; n++) g_hs[hbase + n] = hs[n];
    if (p == 0) g_pa[sc] = cum;
}

// ---------------- chunked scan phase 2: sequential combine over chunks ----------------
__global__ void k_scan_comb() {
    int seq = blockIdx.x;
    int p = threadIdx.x;
    float H[D_STATE];
#pragma unroll
    for (int n = 0; n < D_STATE; n++) H[n] = 0.f;
    for (int c = 0; c < NCH; c++) {
        int sc = seq * NCH + c;
        size_t hbase = (size_t)sc * (HEADDIM * D_STATE) + (size_t)p * D_STATE;
        float pa = g_pa[sc];
#pragma unroll
        for (int n = 0; n < D_STATE; n++) {
            float le = g_hs[hbase + n];
            g_hs[hbase + n] = H[n];     // h_start for chunk c
            H[n] = pa * H[n] + le;
        }
    }
}

// ---------------- chunked scan phase 3: fixup y += cum_t * (C_t . h_start) ----------------
__global__ void k_scan_fix() {
    int sc = blockIdx.x;
    int seq = sc / NCH, c = sc % NCH;
    if (c == 0) return;                // h_start is zero
    int b = seq >> 4, h = seq & 15;
    int p = threadIdx.x;
    int t0 = c * CHL;
    __shared__ float sC[CHL][D_STATE + 1];
    __shared__ float scum[CHL];
    for (int i = p; i < CHL * D_STATE; i += HEADDIM) {
        int tt = i / D_STATE, n = i % D_STATE;
        sC[tt][n] = g_xbc[(size_t)(b*TE + t0 + tt) * CONV_CH + D_MODEL + D_STATE + n];
    }
    if (p < CHL) scum[p] = g_cum[seq * TE + t0 + p];
    float hrow[D_STATE];
    size_t hbase = (size_t)sc * (HEADDIM * D_STATE) + (size_t)p * D_STATE;
#pragma unroll
    for (int n = 0; n < D_STATE; n++) hrow[n] = g_hs[hbase + n];
    __syncthreads();
#pragma unroll 4
    for (int tt = 0; tt < CHL; tt++) {
        float d0 = 0.f, d1 = 0.f;
#pragma unroll
        for (int n = 0; n < D_STATE; n += 2) {
            d0 += hrow[n]   * sC[tt][n];
            d1 += hrow[n+1] * sC[tt][n+1];
        }
        size_t yi = (size_t)(b*TE + t0 + tt) * D_MODEL + h * HEADDIM + p;
        g_y[yi] += scum[tt] * (d0 + d1);
    }
}

// ---------------- y * silu(z), rmsnorm -> fp16 (Wout GEMM A) ----------------
__global__ void k_gatenorm(const float* __restrict__ w) {
    int row = blockIdx.x;
    const float* yr = g_y + (size_t)row * D_MODEL;
    const float* zr = g_zx + (size_t)row * DIN;
    float vals[8];
    float ss = 0.f;
#pragma unroll
    for (int q = 0; q < 8; q++) {
        int j = threadIdx.x + q * 256;
        float z = zr[j];
        float v = yr[j] * siluf(z);
        vals[q] = v; ss += v * v;
    }
    __shared__ float sred[8];
    for (int o = 16; o > 0; o >>= 1) ss += __shfl_down_sync(0xffffffffu, ss, o);
    if ((threadIdx.x & 31) == 0) sred[threadIdx.x >> 5] = ss;
    __syncthreads();
    if (threadIdx.x < 8) {
        float t = sred[threadIdx.x];
        t += __shfl_down_sync(0xffu, t, 4);
        t += __shfl_down_sync(0xffu, t, 2);
        t += __shfl_down_sync(0xffu, t, 1);
        if (threadIdx.x == 0) sred[0] = t;
    }
    __syncthreads();
    float scale = rsqrtf(sred[0] / (float)D_MODEL + 1e-6f);
#pragma unroll
    for (int q = 0; q < 8; q++) {
        int j = threadIdx.x + q * 256;
        g_actF[(size_t)row * D_MODEL + j] = __float2half(vals[q] * scale * w[j]);
    }
}

// ---------------- xe = rmsnorm(xe + mamba_out, loop_norm_w) in place (final) ----------------
__global__ void k_addnorm(const float* __restrict__ w) {
    int row = blockIdx.x;
    float vals[8];
    float ss = 0.f;
#pragma unroll
    for (int q = 0; q < 8; q++) {
        int j = threadIdx.x + q * 256;
        float v = g_xe[(size_t)row * D_MODEL + j] + g_mo[(size_t)row * D_MODEL + j];
        vals[q] = v; ss += v * v;
    }
    __shared__ float sred[8];
    for (int o = 16; o > 0; o >>= 1) ss += __shfl_down_sync(0xffffffffu, ss, o);
    if ((threadIdx.x & 31) == 0) sred[threadIdx.x >> 5] = ss;
    __syncthreads();
    if (threadIdx.x < 8) {
        float t = sred[threadIdx.x];
        t += __shfl_down_sync(0xffu, t, 4);
        t += __shfl_down_sync(0xffu, t, 2);
        t += __shfl_down_sync(0xffu, t, 1);
        if (threadIdx.x == 0) sred[0] = t;
    }
    __syncthreads();
    float scale = rsqrtf(sred[0] / (float)D_MODEL + 1e-6f);
#pragma unroll
    for (int q = 0; q < 8; q++) {
        int j = threadIdx.x + q * 256;
        g_xe[(size_t)row * D_MODEL + j] = vals[q] * scale * w[j];
    }
}

// ---------------- bridge down: t1 = xe @ down^T (rank 64) ----------------
__global__ void k_bridge_down(const float* __restrict__ down) {
    int m = blockIdx.x;
    int r = threadIdx.x >> 2;
    int part = threadIdx.x & 3;
    const float* xr = g_xe + (size_t)m * D_MODEL;
    const float* dr = down + r * D_MODEL;
    float acc = 0.f;
    int k0 = part * 512;
    for (int k = k0; k < k0 + 512; k++) acc += xr[k] * dr[k];
    acc += __shfl_down_sync(0xffffffffu, acc, 1);
    acc += __shfl_down_sync(0xffffffffu, acc, 2);
    if (part == 0) g_t1[m * BRIDGE_RANK + r] = acc;
}

// ---------------- bridge up + residual + extract -> fp16 (logits A) ----------------
__global__ void k_bridge_up(const float* __restrict__ up) {
    int ro = blockIdx.x;
    int jc = blockIdx.y;
    int b = ro >> 9, t = M_PREFIX + (ro & 511);
    int m = b * TE + t;
    __shared__ float s1[BRIDGE_RANK];
    if (threadIdx.x < BRIDGE_RANK) s1[threadIdx.x] = g_t1[m * BRIDGE_RANK + threadIdx.x];
    __syncthreads();
    int j = jc * 256 + threadIdx.x;
    float acc = g_xe[(size_t)m * D_MODEL + j];
#pragma unroll
    for (int r = 0; r < BRIDGE_RANK; r++) acc += s1[r] * up[j * BRIDGE_RANK + r];
    g_finF[(size_t)ro * D_MODEL + j] = __float2half(acc);
}

// ---------------- launch ----------------
extern "C" void kernel_launch(void* const* d_in, const int* in_sizes, int n_in,
                              void* d_out, int out_size) {
    const int*   ids         = (const int*)  d_in[0];
    const float* emb         = (const float*)d_in[1];
    const float* latent      = (const float*)d_in[2];
    const float* gate        = (const float*)d_in[3];
    const float* loop_norm_w = (const float*)d_in[4];
    const float* in_base     = (const float*)d_in[5];
    const float* in_A        = (const float*)d_in[6];
    const float* in_B        = (const float*)d_in[7];
    const float* conv_w      = (const float*)d_in[8];
    const float* conv_b      = (const float*)d_in[9];
    const float* dt_bias     = (const float*)d_in[10];
    const float* A_log       = (const float*)d_in[11];
    const float* D_skip      = (const float*)d_in[12];
    const float* ssm_norm_w  = (const float*)d_in[13];
    const float* out_base    = (const float*)d_in[14];
    const float* out_A       = (const float*)d_in[15];
    const float* out_B       = (const float*)d_in[16];
    const float* bridge_down = (const float*)d_in[17];
    const float* bridge_up   = (const float*)d_in[18];
    float* out = (float*)d_out;

    float *pZx, *pMo;
    __nv_bfloat16 *pWinH, *pWinL, *pActH, *pActL;
    __half *pWoutF, *pActF, *pEmbF, *pFinF;
    cudaGetSymbolAddress((void**)&pZx,    g_zx);
    cudaGetSymbolAddress((void**)&pMo,    g_mo);
    cudaGetSymbolAddress((void**)&pWinH,  g_WinH);
    cudaGetSymbolAddress((void**)&pWinL,  g_WinL);
    cudaGetSymbolAddress((void**)&pActH,  g_actH);
    cudaGetSymbolAddress((void**)&pActL,  g_actL);
    cudaGetSymbolAddress((void**)&pWoutF, g_WoutF);
    cudaGetSymbolAddress((void**)&pActF,  g_actF);
    cudaGetSymbolAddress((void**)&pEmbF,  g_embF);
    cudaGetSymbolAddress((void**)&pFinF,  g_finF);

    cudaFuncSetAttribute(gemm_bf3_64, cudaFuncAttributeMaxDynamicSharedMemorySize, 2 * STG_BF64);
    cudaFuncSetAttribute((const void*)gemm_f16_t<64, 3>,  cudaFuncAttributeMaxDynamicSharedMemorySize, 2 * STG_F64);
    cudaFuncSetAttribute((const void*)gemm_f16_t<128, 2>, cudaFuncAttributeMaxDynamicSharedMemorySize, 2 * STG_F128);

    k_lora2<<<((DIN + D_MODEL) * D_MODEL + 255) / 256, 256>>>(
        in_base, in_A, in_B, out_base, out_A, out_B);
    k_embed<<<(ROWS * D_MODEL + 255) / 256, 256>>>(ids, emb, latent);
    k_prerope<<<ROWS, 1024>>>(gate, 0.0f);

    for (int li = 0; li < MAX_LOOPS; li++) {
        gemm_bf3_64<<<dim3((ROWS + 63) / 64, (DIN + 127) / 128), 256, 2 * STG_BF64>>>(
            pActH, pActL, pWinH, pWinL, pZx, ROWS, DIN, D_MODEL);
        k_conv<<<(ROWS * CONV_CH + 255) / 256, 256>>>(conv_w, conv_b, dt_bias, A_log);
        k_scan_local<<<NSEQ * NCH, HEADDIM>>>(D_skip);
        k_scan_comb<<<NSEQ, HEADDIM>>>();
        k_scan_fix<<<NSEQ * NCH, HEADDIM>>>();
        k_gatenorm<<<ROWS, 256>>>(ssm_norm_w);
        gemm_f16_t<64, 3><<<dim3((ROWS + 63) / 64, D_MODEL / 128), 256, 2 * STG_F64>>>(
            pActF, pWoutF, pMo, ROWS, D_MODEL, D_MODEL);
        if (li + 1 < MAX_LOOPS)
            k_addnorm_rope<<<ROWS, 256>>>(loop_norm_w, gate, (float)(li + 1));
        else
            k_addnorm<<<ROWS, 256>>>(loop_norm_w);
    }

    k_bridge_down<<<ROWS, 256>>>(bridge_down);
    k_bridge_up<<<dim3(OUTROWS, D_MODEL / 256), 256>>>(bridge_up);
    {
        size_t n4 = (size_t)VOCAB * D_MODEL / 4;
        k_cvt_f16<<<(unsigned)((n4 + 255) / 256), 256>>>(emb, pEmbF, n4);
    }
    gemm_f16_t<128, 2><<<dim3(OUTROWS / 128, VOCAB / 128), 256, 2 * STG_F128>>>(
        pFinF, pEmbF, out, OUTROWS, VOCAB, D_MODEL);
}

// round 9
// speedup vs baseline: 1.0071x; 1.0071x over previous
#include <cuda_runtime.h>
#include <cuda_bf16.h>
#include <cuda_fp16.h>
#include <math.h>
#include <stdint.h>

#define D_MODEL 2048
#define D_STATE 32
#define HEADDIM 128
#define NHEADS 16
#define D_CONVK 4
#define M_PREFIX 8
#define MAX_LOOPS 6
#define BRIDGE_RANK 64
#define VOCAB 50432
#define LORA_RANK 4
#define BSZ 2
#define TLEN 512
#define TE (M_PREFIX + TLEN)     /* 520 */
#define ROWS (BSZ * TE)          /* 1040 */
#define DIN (2*D_MODEL + 2*D_STATE + NHEADS)  /* 4176 */
#define CONV_CH (D_MODEL + 2*D_STATE)         /* 2112 */
#define OUTROWS (BSZ * TLEN)     /* 1024 */
#define NSEQ (BSZ * NHEADS)      /* 32 */
#define NCH 13
#define CHL 40                   /* NCH * CHL == TE */

// ---------------- scratch (static device globals; no allocs) ----------------
__device__ float g_xe[ROWS * D_MODEL];
__device__ float g_xp[OUTROWS * D_MODEL];
__device__ float g_zx[ROWS * DIN];
__device__ float g_xbc[ROWS * CONV_CH];
__device__ float g_dt[ROWS * NHEADS];
__device__ float g_dA[ROWS * NHEADS];
__device__ float g_y[ROWS * D_MODEL];
__device__ float g_mo[ROWS * D_MODEL];
__device__ float g_t1[ROWS * BRIDGE_RANK];
// chunked-scan state
__device__ float g_hs[(size_t)NSEQ * NCH * HEADDIM * D_STATE];
__device__ float g_pa[NSEQ * NCH];
__device__ float g_cum[NSEQ * TE];

// bf16 hi/lo operand buffers (Win GEMM)
__device__ __nv_bfloat16 g_WinH[DIN * D_MODEL],   g_WinL[DIN * D_MODEL];
__device__ __nv_bfloat16 g_actH[ROWS * D_MODEL],  g_actL[ROWS * D_MODEL];
// fp16 operand buffers (Wout GEMM + logits GEMM, single-pass)
__device__ __half g_WoutF[D_MODEL * D_MODEL];
__device__ __half g_actF[ROWS * D_MODEL];
__device__ __half g_embF[(size_t)VOCAB * D_MODEL];
__device__ __half g_finF[OUTROWS * D_MODEL];

__device__ __forceinline__ float siluf(float x) { return x / (1.0f + expf(-x)); }

__device__ __forceinline__ uint32_t smem_u32(const void* p) {
    uint32_t a;
    asm("{ .reg .u64 t; cvta.to.shared.u64 t, %1; cvt.u32.u64 %0, t; }" : "=r"(a) : "l"(p));
    return a;
}
__device__ __forceinline__ void cpa16(uint32_t dst, const void* src, uint32_t bytes) {
    asm volatile("cp.async.cg.shared.global [%0], [%1], 16, %2;" :: "r"(dst), "l"(src), "r"(bytes));
}
__device__ __forceinline__ void split1(float v, __nv_bfloat16* hi, __nv_bfloat16* lo, size_t i) {
    __nv_bfloat16 h = __float2bfloat16(v);
    hi[i] = h;
    lo[i] = __float2bfloat16(v - __bfloat162float(h));
}

// ================= shared GEMM tile constants =================
#define KC 32
#define SROW 40
#define AB128 (128 * SROW * 2)      /* 10240 bytes per array */
#define STG_BF (4 * AB128)          /* bf3: AH AL BH BL */
#define STG_F  (2 * AB128)          /* f16: A B */

#define LDSM4(r, addr) \
    asm volatile("ldmatrix.sync.aligned.m8n8.x4.shared.b16 {%0,%1,%2,%3}, [%4];" \
        : "=r"((r)[0]), "=r"((r)[1]), "=r"((r)[2]), "=r"((r)[3]) : "r"(addr))

#define MMA_BF(d, a, b0, b1) \
    asm volatile("mma.sync.aligned.m16n8k16.row.col.f32.bf16.bf16.f32 " \
        "{%0,%1,%2,%3},{%4,%5,%6,%7},{%8,%9},{%0,%1,%2,%3};" \
        : "+f"((d)[0]), "+f"((d)[1]), "+f"((d)[2]), "+f"((d)[3]) \
        : "r"((a)[0]), "r"((a)[1]), "r"((a)[2]), "r"((a)[3]), "r"(b0), "r"(b1))

#define MMA_F16(d, a, b0, b1) \
    asm volatile("mma.sync.aligned.m16n8k16.row.col.f32.f16.f16.f32 " \
        "{%0,%1,%2,%3},{%4,%5,%6,%7},{%8,%9},{%0,%1,%2,%3};" \
        : "+f"((d)[0]), "+f"((d)[1]), "+f"((d)[2]), "+f"((d)[3]) \
        : "r"((a)[0]), "r"((a)[1]), "r"((a)[2]), "r"((a)[3]), "r"(b0), "r"(b1))

// ---- epilogue: 128x128 tile, warp grid 2x4, warp tile 64x32 ----
__device__ __forceinline__ void epi_store(float acc[4][4][4], float* C,
        int m0, int n0, int M, int N, int wm, int wn, int lane) {
#pragma unroll
    for (int mt = 0; mt < 4; mt++) {
#pragma unroll
        for (int nt = 0; nt < 4; nt++) {
            int m = m0 + wm * 64 + mt * 16 + (lane >> 2);
            int n = n0 + wn * 32 + nt * 8 + (lane & 3) * 2;
            if (n < N) {
                if (m < M) {
                    float2 v = make_float2(acc[mt][nt][0], acc[mt][nt][1]);
                    *(float2*)(C + (size_t)m * N + n) = v;
                }
                if (m + 8 < M) {
                    float2 v = make_float2(acc[mt][nt][2], acc[mt][nt][3]);
                    *(float2*)(C + (size_t)(m + 8) * N + n) = v;
                }
            }
        }
    }
}

// ================= bf16x3 GEMM (Win): C = A @ B^T, TM=128 =================
// Precomputed per-thread load addressing: per unrolled i, the array index is
// compile-time; only `base + offs[i] + k0` remains in the hot loop.
__global__ void __launch_bounds__(256, 2) gemm_bf3(
        const __nv_bfloat16* __restrict__ AH, const __nv_bfloat16* __restrict__ AL,
        const __nv_bfloat16* __restrict__ BH, const __nv_bfloat16* __restrict__ BL,
        float* __restrict__ C, int M, int N, int K) {
    extern __shared__ __align__(16) char smdyn[];
    uint32_t sb = smem_u32(smdyn);

    int tid = threadIdx.x, lane = tid & 31, wid = tid >> 5;
    int wm = wid >> 2, wn = wid & 3;
    int m0 = blockIdx.x * 128, n0 = blockIdx.y * 128;

    float acc[4][4][4] = {};

    // --- precompute load addressing (i: 0,1=AH 2,3=AL 4,5=BH 6,7=BL) ---
    const __nv_bfloat16* bases[4] = {AH, AL, BH, BL};
    uint32_t offs[8], sdst[8], vmask = 0;
    {
        int row_e = tid >> 2, col = tid & 3;
#pragma unroll
        for (int i = 0; i < 8; i++) {
            int row = row_e + (i & 1) * 64;
            int g   = ((i < 4) ? m0 : n0) + row;
            int lim = (i < 4) ? M : N;
            int gc  = (g < lim) ? g : 0;
            if (g < lim) vmask |= (1u << i);
            offs[i] = (uint32_t)gc * (uint32_t)K + (uint32_t)(col * 8);
            sdst[i] = (uint32_t)((i >> 1) * AB128 + row * 80 + col * 16);
        }
    }
    auto issue_loads = [&](uint32_t stagebase, int k0) {
#pragma unroll
        for (int i = 0; i < 8; i++)
            cpa16(stagebase + sdst[i], bases[i >> 1] + offs[i] + k0,
                  ((vmask >> i) & 1u) * 16u);
    };

    uint32_t aRow = (uint32_t)(wm * 64 + (lane & 15));
    uint32_t aColB = (uint32_t)((lane >> 4) * 8) * 2;
    uint32_t bRow = (uint32_t)(wn * 32 + ((lane >> 4) & 1) * 8 + (lane & 7));
    uint32_t bColB = (uint32_t)(((lane >> 3) & 1) * 8) * 2;

    const int nch = K >> 5;
    issue_loads(sb, 0);
    asm volatile("cp.async.commit_group;" ::: "memory");
    for (int ch = 0; ch < nch; ch++) {
        asm volatile("cp.async.wait_group 0;" ::: "memory");
        __syncthreads();
        uint32_t uS = sb + (uint32_t)((ch & 1) * STG_BF);
        if (ch + 1 < nch)
            issue_loads(sb + (uint32_t)(((ch + 1) & 1) * STG_BF), (ch + 1) * KC);
        asm volatile("cp.async.commit_group;" ::: "memory");
        uint32_t uAH = uS, uAL = uS + AB128, uBH = uS + 2*AB128, uBL = uS + 3*AB128;
#pragma unroll
        for (int ks = 0; ks < 2; ks++) {
            uint32_t kcb = (uint32_t)(ks * 16) * 2;
            uint32_t a[4][4], b[2][4];
            // pass 1: Ah * Bh
#pragma unroll
            for (int mt = 0; mt < 4; mt++)
                LDSM4(a[mt], uAH + ((aRow + mt * 16) * SROW) * 2 + kcb + aColB);
#pragma unroll
            for (int bt = 0; bt < 2; bt++)
                LDSM4(b[bt], uBH + ((bRow + bt * 16) * SROW) * 2 + kcb + bColB);
#pragma unroll
            for (int mt = 0; mt < 4; mt++)
#pragma unroll
                for (int nt = 0; nt < 4; nt++)
                    MMA_BF(acc[mt][nt], a[mt], b[nt >> 1][(nt & 1) * 2], b[nt >> 1][(nt & 1) * 2 + 1]);
            // pass 2: Ah * Bl (reuse a)
#pragma unroll
            for (int bt = 0; bt < 2; bt++)
                LDSM4(b[bt], uBL + ((bRow + bt * 16) * SROW) * 2 + kcb + bColB);
#pragma unroll
            for (int mt = 0; mt < 4; mt++)
#pragma unroll
                for (int nt = 0; nt < 4; nt++)
                    MMA_BF(acc[mt][nt], a[mt], b[nt >> 1][(nt & 1) * 2], b[nt >> 1][(nt & 1) * 2 + 1]);
            // pass 3: Al * Bh (reload both)
#pragma unroll
            for (int mt = 0; mt < 4; mt++)
                LDSM4(a[mt], uAL + ((aRow + mt * 16) * SROW) * 2 + kcb + aColB);
#pragma unroll
            for (int bt = 0; bt < 2; bt++)
                LDSM4(b[bt], uBH + ((bRow + bt * 16) * SROW) * 2 + kcb + bColB);
#pragma unroll
            for (int mt = 0; mt < 4; mt++)
#pragma unroll
                for (int nt = 0; nt < 4; nt++)
                    MMA_BF(acc[mt][nt], a[mt], b[nt >> 1][(nt & 1) * 2], b[nt >> 1][(nt & 1) * 2 + 1]);
        }
    }
    epi_store(acc, C, m0, n0, M, N, wm, wn, lane);
}

// ================= fp16 single-pass GEMM (Wout + logits): C = A @ B^T, TM=128 =================
__global__ void __launch_bounds__(256, 2) gemm_f16(
        const __half* __restrict__ A, const __half* __restrict__ B,
        float* __restrict__ C, int M, int N, int K) {
    extern __shared__ __align__(16) char smdyn[];
    uint32_t sb = smem_u32(smdyn);

    int tid = threadIdx.x, lane = tid & 31, wid = tid >> 5;
    int wm = wid >> 2, wn = wid & 3;
    int m0 = blockIdx.x * 128, n0 = blockIdx.y * 128;

    float acc[4][4][4] = {};

    // --- precompute load addressing (i: 0,1=A 2,3=B) ---
    const __half* bases[2] = {A, B};
    uint32_t offs[4], sdst[4], vmask = 0;
    {
        int row_e = tid >> 2, col = tid & 3;
#pragma unroll
        for (int i = 0; i < 4; i++) {
            int row = row_e + (i & 1) * 64;
            int g   = ((i < 2) ? m0 : n0) + row;
            int lim = (i < 2) ? M : N;
            int gc  = (g < lim) ? g : 0;
            if (g < lim) vmask |= (1u << i);
            offs[i] = (uint32_t)gc * (uint32_t)K + (uint32_t)(col * 8);
            sdst[i] = (uint32_t)((i >> 1) * AB128 + row * 80 + col * 16);
        }
    }
    auto issue_loads = [&](uint32_t stagebase, int k0) {
#pragma unroll
        for (int i = 0; i < 4; i++)
            cpa16(stagebase + sdst[i], bases[i >> 1] + offs[i] + k0,
                  ((vmask >> i) & 1u) * 16u);
    };

    uint32_t aRow = (uint32_t)(wm * 64 + (lane & 15));
    uint32_t aColB = (uint32_t)((lane >> 4) * 8) * 2;
    uint32_t bRow = (uint32_t)(wn * 32 + ((lane >> 4) & 1) * 8 + (lane & 7));
    uint32_t bColB = (uint32_t)(((lane >> 3) & 1) * 8) * 2;

    const int nch = K >> 5;
    issue_loads(sb, 0);
    asm volatile("cp.async.commit_group;" ::: "memory");
    for (int ch = 0; ch < nch; ch++) {
        asm volatile("cp.async.wait_group 0;" ::: "memory");
        __syncthreads();
        uint32_t uS = sb + (uint32_t)((ch & 1) * STG_F);
        if (ch + 1 < nch)
            issue_loads(sb + (uint32_t)(((ch + 1) & 1) * STG_F), (ch + 1) * KC);
        asm volatile("cp.async.commit_group;" ::: "memory");
        uint32_t uA = uS, uB = uS + AB128;
#pragma unroll
        for (int ks = 0; ks < 2; ks++) {
            uint32_t kcb = (uint32_t)(ks * 16) * 2;
            uint32_t a[4][4], b[2][4];
#pragma unroll
            for (int mt = 0; mt < 4; mt++)
                LDSM4(a[mt], uA + ((aRow + mt * 16) * SROW) * 2 + kcb + aColB);
#pragma unroll
            for (int bt = 0; bt < 2; bt++)
                LDSM4(b[bt], uB + ((bRow + bt * 16) * SROW) * 2 + kcb + bColB);
#pragma unroll
            for (int mt = 0; mt < 4; mt++)
#pragma unroll
                for (int nt = 0; nt < 4; nt++)
                    MMA_F16(acc[mt][nt], a[mt], b[nt >> 1][(nt & 1) * 2], b[nt >> 1][(nt & 1) * 2 + 1]);
        }
    }
    epi_store(acc, C, m0, n0, M, N, wm, wn, lane);
}

// ---------------- fused LoRA fold: Win -> bf16 hi/lo, Wout -> fp16 ----------------
__global__ void k_lora2(const float* __restrict__ in_base, const float* __restrict__ in_A,
                        const float* __restrict__ in_B,
                        const float* __restrict__ out_base, const float* __restrict__ out_A,
                        const float* __restrict__ out_B) {
    int i = blockIdx.x * 256 + threadIdx.x;
    const int T1 = DIN * D_MODEL;
    if (i < T1) {
        int r = i / D_MODEL, c = i % D_MODEL;
        float s = 0.f;
#pragma unroll
        for (int q = 0; q < LORA_RANK; q++) s += in_B[r*LORA_RANK + q] * in_A[q*D_MODEL + c];
        split1(in_base[i] + 2.0f * s, g_WinH, g_WinL, i);
    } else {
        int j = i - T1;
        if (j >= D_MODEL * D_MODEL) return;
        int r = j / D_MODEL, c = j % D_MODEL;
        float s = 0.f;
#pragma unroll
        for (int q = 0; q < LORA_RANK; q++) s += out_B[r*LORA_RANK + q] * out_A[q*D_MODEL + c];
        g_WoutF[j] = __float2half(out_base[j] + 2.0f * s);
    }
}

// ---------------- f32 -> fp16 convert (vectorized), for emb ----------------
__global__ void k_cvt_f16(const float* __restrict__ in, __half* __restrict__ o, size_t n4) {
    size_t i = (size_t)blockIdx.x * 256 + threadIdx.x;
    if (i >= n4) return;
    float4 v = *(const float4*)(in + i * 4);
    __half2 p0 = __floats2half2_rn(v.x, v.y);
    __half2 p1 = __floats2half2_rn(v.z, v.w);
    uint2 pk;
    pk.x = *(uint32_t*)&p0;
    pk.y = *(uint32_t*)&p1;
    *(uint2*)(o + i * 4) = pk;
}

// ---------------- embedding gather + latent prefix ----------------
__global__ void k_embed(const int* __restrict__ ids, const float* __restrict__ emb,
                        const float* __restrict__ latent) {
    int i = blockIdx.x * 256 + threadIdx.x;
    if (i >= ROWS * D_MODEL) return;
    int row = i / D_MODEL, c = i % D_MODEL;
    int b = row / TE, t = row % TE;
    float v;
    if (t < M_PREFIX) {
        v = latent[t * D_MODEL + c];
    } else {
        int tok = ids[b * TLEN + (t - M_PREFIX)];
        v = emb[(size_t)tok * D_MODEL + c];
        g_xp[(b * TLEN + (t - M_PREFIX)) * D_MODEL + c] = v;
    }
    g_xe[i] = v;
}

// ---------------- lifeline + RoPE (loop start); emits f32 residual + bf16 hi/lo ----------------
__global__ void k_prerope(const float* __restrict__ gate, float loop_i) {
    int row = blockIdx.x;
    int j = threadIdx.x;              // pair index 0..1023
    int b = row / TE, t = row % TE;
    float v0 = g_xe[row * D_MODEL + 2*j];
    float v1 = g_xe[row * D_MODEL + 2*j + 1];
    if (t >= M_PREFIX) {
        int pr = (b * TLEN + t - M_PREFIX) * D_MODEL;
        v0 += gate[2*j]     * g_xp[pr + 2*j];
        v1 += gate[2*j + 1] * g_xp[pr + 2*j + 1];
    }
    float freq = loop_i * powf(10000.0f, -(float)(2*j) / (float)D_MODEL);
    float s, c;
    sincosf(freq, &s, &c);
    float r0 = v0 * c - v1 * s;
    float r1 = v1 * c + v0 * s;
    size_t o = (size_t)row * D_MODEL + 2*j;
    g_xe[o] = r0; g_xe[o + 1] = r1;
    split1(r0, g_actH, g_actL, o);
    split1(r1, g_actH, g_actL, o + 1);
}

// ---------------- fused: xe = rmsnorm(xe + mo) -> lifeline -> rope(next loop) ----------------
__global__ void k_addnorm_rope(const float* __restrict__ w, const float* __restrict__ gate,
                               float loop_i) {
    int row = blockIdx.x;
    int b = row / TE, t = row % TE;
    float v[4][2];
    float ss = 0.f;
#pragma unroll
    for (int q = 0; q < 4; q++) {
        int j = threadIdx.x + q * 256;       // pair index
        size_t o = (size_t)row * D_MODEL + 2*j;
        float a0 = g_xe[o]     + g_mo[o];
        float a1 = g_xe[o + 1] + g_mo[o + 1];
        v[q][0] = a0; v[q][1] = a1;
        ss += a0 * a0 + a1 * a1;
    }
    __shared__ float sred[8];
    for (int o = 16; o > 0; o >>= 1) ss += __shfl_down_sync(0xffffffffu, ss, o);
    if ((threadIdx.x & 31) == 0) sred[threadIdx.x >> 5] = ss;
    __syncthreads();
    if (threadIdx.x < 8) {
        float tt = sred[threadIdx.x];
        tt += __shfl_down_sync(0xffu, tt, 4);
        tt += __shfl_down_sync(0xffu, tt, 2);
        tt += __shfl_down_sync(0xffu, tt, 1);
        if (threadIdx.x == 0) sred[0] = tt;
    }
    __syncthreads();
    float scale = rsqrtf(sred[0] / (float)D_MODEL + 1e-6f);
#pragma unroll
    for (int q = 0; q < 4; q++) {
        int j = threadIdx.x + q * 256;
        size_t o = (size_t)row * D_MODEL + 2*j;
        float r0 = v[q][0] * scale * w[2*j];
        float r1 = v[q][1] * scale * w[2*j + 1];
        if (t >= M_PREFIX) {
            size_t pr = (size_t)(b * TLEN + t - M_PREFIX) * D_MODEL;
            r0 += gate[2*j]     * g_xp[pr + 2*j];
            r1 += gate[2*j + 1] * g_xp[pr + 2*j + 1];
        }
        float freq = loop_i * powf(10000.0f, -(float)(2*j) / (float)D_MODEL);
        float s, c;
        sincosf(freq, &s, &c);
        float o0 = r0 * c - r1 * s;
        float o1 = r1 * c + r0 * s;
        g_xe[o] = o0; g_xe[o + 1] = o1;
        split1(o0, g_actH, g_actL, o);
        split1(o1, g_actH, g_actL, o + 1);
    }
}

// ---------------- conv (K=4) + bias + silu, fused with dt/dA ----------------
__global__ void k_conv(const float* __restrict__ cw, const float* __restrict__ cb,
                       const float* __restrict__ dt_bias, const float* __restrict__ A_log) {
    int i = blockIdx.x * 256 + threadIdx.x;
    if (i < ROWS * NHEADS) {
        int row = i / NHEADS, h = i % NHEADS;
        float x = g_zx[(size_t)row * DIN + (2*D_MODEL + 2*D_STATE) + h] + dt_bias[h];
        float sp = (x > 20.f) ? x : log1pf(expf(x));
        g_dt[i] = sp;
        g_dA[i] = expf(-expf(A_log[h]) * sp);
    }
    if (i >= ROWS * CONV_CH) return;
    int row = i / CONV_CH, c = i % CONV_CH;
    int b = row / TE, t = row % TE;
    float acc = cb[c];
#pragma unroll
    for (int k = 0; k < D_CONVK; k++) {
        int tt = t - (D_CONVK - 1) + k;
        if (tt >= 0) acc += g_zx[((size_t)(b*TE + tt)) * DIN + D_MODEL + c] * cw[c*D_CONVK + k];
    }
    g_xbc[i] = siluf(acc);
}

// ---------------- chunked scan phase 1: local scan per (seq, chunk) ----------------
__global__ void k_scan_local(const float* __restrict__ D_skip) {
    int sc = blockIdx.x;               // seq * NCH + c
    int seq = sc / NCH, c = sc % NCH;
    int b = seq >> 4, h = seq & 15;
    int p = threadIdx.x;
    int t0 = c * CHL;
    float hs[D_STATE];
#pragma unroll
    for (int n = 0; n < D_STATE; n++) hs[n] = 0.f;
    __shared__ float sB[2][D_STATE], sC[2][D_STATE];
    float Dh = D_skip[h];
    float cum = 1.f;

    const float* row0 = g_xbc + (size_t)(b*TE + t0) * CONV_CH;
    if (p < 2*D_STATE) {
        float v = row0[D_MODEL + p];
        if (p < D_STATE) sB[0][p] = v; else sC[0][p - D_STATE] = v;
    }
    float x   = row0[h * HEADDIM + p];
    float dAv = g_dA[(size_t)(b*TE + t0) * NHEADS + h];
    float dtv = g_dt[(size_t)(b*TE + t0) * NHEADS + h];
    __syncthreads();

    for (int tt = 0; tt < CHL; tt++) {
        int t = t0 + tt;
        int tn = (tt + 1 < CHL) ? t + 1 : t;
        size_t rn = (size_t)(b*TE + tn);
        const float* rown = g_xbc + rn * CONV_CH;
        float xn   = rown[h * HEADDIM + p];
        float dAn  = g_dA[rn * NHEADS + h];
        float dtn  = g_dt[rn * NHEADS + h];
        int nxt = (tt + 1) & 1, cur = tt & 1;
        if (p < 2*D_STATE) {
            float v = rown[D_MODEL + p];
            if (p < D_STATE) sB[nxt][p] = v; else sC[nxt][p - D_STATE] = v;
        }
        cum *= dAv;
        float coef = dtv * x;
        float a0 = 0.f, a1 = 0.f, a2 = 0.f, a3 = 0.f;
#pragma unroll
        for (int n = 0; n < D_STATE; n += 4) {
            hs[n+0] = dAv * hs[n+0] + coef * sB[cur][n+0]; a0 += hs[n+0] * sC[cur][n+0];
            hs[n+1] = dAv * hs[n+1] + coef * sB[cur][n+1]; a1 += hs[n+1] * sC[cur][n+1];
            hs[n+2] = dAv * hs[n+2] + coef * sB[cur][n+2]; a2 += hs[n+2] * sC[cur][n+2];
            hs[n+3] = dAv * hs[n+3] + coef * sB[cur][n+3]; a3 += hs[n+3] * sC[cur][n+3];
        }
        g_y[(size_t)(b*TE + t) * D_MODEL + h * HEADDIM + p] = (a0 + a1) + (a2 + a3) + Dh * x;
        if (p == 0) g_cum[seq * TE + t] = cum;
        __syncthreads();
        x = xn; dAv = dAn; dtv = dtn;
    }
    size_t hbase = (size_t)sc * (HEADDIM * D_STATE) + (size_t)p * D_STATE;
#pragma unroll
    for (int n = 0; n < D_STATE; n++) g_hs[hbase + n] = hs[n];
    if (p == 0) g_pa[sc] = cum;
}

// ---------------- chunked scan phase 2: sequential combine over chunks ----------------
__global__ void k_scan_comb() {
    int seq = blockIdx.x;
    int p = threadIdx.x;
    float H[D_STATE];
#pragma unroll
    for (int n = 0; n < D_STATE; n++) H[n] = 0.f;
    for (int c = 0; c < NCH; c++) {
        int sc = seq * NCH + c;
        size_t hbase = (size_t)sc * (HEADDIM * D_STATE) + (size_t)p * D_STATE;
        float pa = g_pa[sc];
#pragma unroll
        for (int n = 0; n < D_STATE; n++) {
            float le = g_hs[hbase + n];
            g_hs[hbase + n] = H[n];     // h_start for chunk c
            H[n] = pa * H[n] + le;
        }
    }
}

// ---------------- chunked scan phase 3: fixup y += cum_t * (C_t . h_start) ----------------
__global__ void k_scan_fix() {
    int sc = blockIdx.x;
    int seq = sc / NCH, c = sc % NCH;
    if (c == 0) return;                // h_start is zero
    int b = seq >> 4, h = seq & 15;
    int p = threadIdx.x;
    int t0 = c * CHL;
    __shared__ float sC[CHL][D_STATE + 1];
    __shared__ float scum[CHL];
    for (int i = p; i < CHL * D_STATE; i += HEADDIM) {
        int tt = i / D_STATE, n = i % D_STATE;
        sC[tt][n] = g_xbc[(size_t)(b*TE + t0 + tt) * CONV_CH + D_MODEL + D_STATE + n];
    }
    if (p < CHL) scum[p] = g_cum[seq * TE + t0 + p];
    float hrow[D_STATE];
    size_t hbase = (size_t)sc * (HEADDIM * D_STATE) + (size_t)p * D_STATE;
#pragma unroll
    for (int n = 0; n < D_STATE; n++) hrow[n] = g_hs[hbase + n];
    __syncthreads();
#pragma unroll 4
    for (int tt = 0; tt < CHL; tt++) {
        float d0 = 0.f, d1 = 0.f;
#pragma unroll
        for (int n = 0; n < D_STATE; n += 2) {
            d0 += hrow[n]   * sC[tt][n];
            d1 += hrow[n+1] * sC[tt][n+1];
        }
        size_t yi = (size_t)(b*TE + t0 + tt) * D_MODEL + h * HEADDIM + p;
        g_y[yi] += scum[tt] * (d0 + d1);
    }
}

// ---------------- y * silu(z), rmsnorm -> fp16 (Wout GEMM A) ----------------
__global__ void k_gatenorm(const float* __restrict__ w) {
    int row = blockIdx.x;
    const float* yr = g_y + (size_t)row * D_MODEL;
    const float* zr = g_zx + (size_t)row * DIN;
    float vals[8];
    float ss = 0.f;
#pragma unroll
    for (int q = 0; q < 8; q++) {
        int j = threadIdx.x + q * 256;
        float z = zr[j];
        float v = yr[j] * siluf(z);
        vals[q] = v; ss += v * v;
    }
    __shared__ float sred[8];
    for (int o = 16; o > 0; o >>= 1) ss += __shfl_down_sync(0xffffffffu, ss, o);
    if ((threadIdx.x & 31) == 0) sred[threadIdx.x >> 5] = ss;
    __syncthreads();
    if (threadIdx.x < 8) {
        float t = sred[threadIdx.x];
        t += __shfl_down_sync(0xffu, t, 4);
        t += __shfl_down_sync(0xffu, t, 2);
        t += __shfl_down_sync(0xffu, t, 1);
        if (threadIdx.x == 0) sred[0] = t;
    }
    __syncthreads();
    float scale = rsqrtf(sred[0] / (float)D_MODEL + 1e-6f);
#pragma unroll
    for (int q = 0; q < 8; q++) {
        int j = threadIdx.x + q * 256;
        g_actF[(size_t)row * D_MODEL + j] = __float2half(vals[q] * scale * w[j]);
    }
}

// ---------------- xe = rmsnorm(xe + mamba_out, loop_norm_w) in place (final) ----------------
__global__ void k_addnorm(const float* __restrict__ w) {
    int row = blockIdx.x;
    float vals[8];
    float ss = 0.f;
#pragma unroll
    for (int q = 0; q < 8; q++) {
        int j = threadIdx.x + q * 256;
        float v = g_xe[(size_t)row * D_MODEL + j] + g_mo[(size_t)row * D_MODEL + j];
        vals[q] = v; ss += v * v;
    }
    __shared__ float sred[8];
    for (int o = 16; o > 0; o >>= 1) ss += __shfl_down_sync(0xffffffffu, ss, o);
    if ((threadIdx.x & 31) == 0) sred[threadIdx.x >> 5] = ss;
    __syncthreads();
    if (threadIdx.x < 8) {
        float t = sred[threadIdx.x];
        t += __shfl_down_sync(0xffu, t, 4);
        t += __shfl_down_sync(0xffu, t, 2);
        t += __shfl_down_sync(0xffu, t, 1);
        if (threadIdx.x == 0) sred[0] = t;
    }
    __syncthreads();
    float scale = rsqrtf(sred[0] / (float)D_MODEL + 1e-6f);
#pragma unroll
    for (int q = 0; q < 8; q++) {
        int j = threadIdx.x + q * 256;
        g_xe[(size_t)row * D_MODEL + j] = vals[q] * scale * w[j];
    }
}

// ---------------- bridge down: t1 = xe @ down^T (rank 64) ----------------
__global__ void k_bridge_down(const float* __restrict__ down) {
    int m = blockIdx.x;
    int r = threadIdx.x >> 2;
    int part = threadIdx.x & 3;
    const float* xr = g_xe + (size_t)m * D_MODEL;
    const float* dr = down + r * D_MODEL;
    float acc = 0.f;
    int k0 = part * 512;
    for (int k = k0; k < k0 + 512; k++) acc += xr[k] * dr[k];
    acc += __shfl_down_sync(0xffffffffu, acc, 1);
    acc += __shfl_down_sync(0xffffffffu, acc, 2);
    if (part == 0) g_t1[m * BRIDGE_RANK + r] = acc;
}

// ---------------- bridge up + residual + extract -> fp16 (logits A) ----------------
__global__ void k_bridge_up(const float* __restrict__ up) {
    int ro = blockIdx.x;
    int jc = blockIdx.y;
    int b = ro >> 9, t = M_PREFIX + (ro & 511);
    int m = b * TE + t;
    __shared__ float s1[BRIDGE_RANK];
    if (threadIdx.x < BRIDGE_RANK) s1[threadIdx.x] = g_t1[m * BRIDGE_RANK + threadIdx.x];
    __syncthreads();
    int j = jc * 256 + threadIdx.x;
    float acc = g_xe[(size_t)m * D_MODEL + j];
#pragma unroll
    for (int r = 0; r < BRIDGE_RANK; r++) acc += s1[r] * up[j * BRIDGE_RANK + r];
    g_finF[(size_t)ro * D_MODEL + j] = __float2half(acc);
}

// ---------------- launch ----------------
extern "C" void kernel_launch(void* const* d_in, const int* in_sizes, int n_in,
                              void* d_out, int out_size) {
    const int*   ids         = (const int*)  d_in[0];
    const float* emb         = (const float*)d_in[1];
    const float* latent      = (const float*)d_in[2];
    const float* gate        = (const float*)d_in[3];
    const float* loop_norm_w = (const float*)d_in[4];
    const float* in_base     = (const float*)d_in[5];
    const float* in_A        = (const float*)d_in[6];
    const float* in_B        = (const float*)d_in[7];
    const float* conv_w      = (const float*)d_in[8];
    const float* conv_b      = (const float*)d_in[9];
    const float* dt_bias     = (const float*)d_in[10];
    const float* A_log       = (const float*)d_in[11];
    const float* D_skip      = (const float*)d_in[12];
    const float* ssm_norm_w  = (const float*)d_in[13];
    const float* out_base    = (const float*)d_in[14];
    const float* out_A       = (const float*)d_in[15];
    const float* out_B       = (const float*)d_in[16];
    const float* bridge_down = (const float*)d_in[17];
    const float* bridge_up   = (const float*)d_in[18];
    float* out = (float*)d_out;

    float *pZx, *pMo;
    __nv_bfloat16 *pWinH, *pWinL, *pActH, *pActL;
    __half *pWoutF, *pActF, *pEmbF, *pFinF;
    cudaGetSymbolAddress((void**)&pZx,    g_zx);
    cudaGetSymbolAddress((void**)&pMo,    g_mo);
    cudaGetSymbolAddress((void**)&pWinH,  g_WinH);
    cudaGetSymbolAddress((void**)&pWinL,  g_WinL);
    cudaGetSymbolAddress((void**)&pActH,  g_actH);
    cudaGetSymbolAddress((void**)&pActL,  g_actL);
    cudaGetSymbolAddress((void**)&pWoutF, g_WoutF);
    cudaGetSymbolAddress((void**)&pActF,  g_actF);
    cudaGetSymbolAddress((void**)&pEmbF,  g_embF);
    cudaGetSymbolAddress((void**)&pFinF,  g_finF);

    cudaFuncSetAttribute(gemm_bf3, cudaFuncAttributeMaxDynamicSharedMemorySize, 2 * STG_BF);
    cudaFuncSetAttribute(gemm_f16, cudaFuncAttributeMaxDynamicSharedMemorySize, 2 * STG_F);

    k_lora2<<<((DIN + D_MODEL) * D_MODEL + 255) / 256, 256>>>(
        in_base, in_A, in_B, out_base, out_A, out_B);
    k_embed<<<(ROWS * D_MODEL + 255) / 256, 256>>>(ids, emb, latent);
    k_prerope<<<ROWS, 1024>>>(gate, 0.0f);

    for (int li = 0; li < MAX_LOOPS; li++) {
        gemm_bf3<<<dim3((ROWS + 127) / 128, (DIN + 127) / 128), 256, 2 * STG_BF>>>(
            pActH, pActL, pWinH, pWinL, pZx, ROWS, DIN, D_MODEL);
        k_conv<<<(ROWS * CONV_CH + 255) / 256, 256>>>(conv_w, conv_b, dt_bias, A_log);
        k_scan_local<<<NSEQ * NCH, HEADDIM>>>(D_skip);
        k_scan_comb<<<NSEQ, HEADDIM>>>();
        k_scan_fix<<<NSEQ * NCH, HEADDIM>>>();
        k_gatenorm<<<ROWS, 256>>>(ssm_norm_w);
        gemm_f16<<<dim3((ROWS + 127) / 128, D_MODEL / 128), 256, 2 * STG_F>>>(
            pActF, pWoutF, pMo, ROWS, D_MODEL, D_MODEL);
        if (li + 1 < MAX_LOOPS)
            k_addnorm_rope<<<ROWS, 256>>>(loop_norm_w, gate, (float)(li + 1));
        else
            k_addnorm<<<ROWS, 256>>>(loop_norm_w);
    }

    k_bridge_down<<<ROWS, 256>>>(bridge_down);
    k_bridge_up<<<dim3(OUTROWS, D_MODEL / 256), 256>>>(bridge_up);
    {
        size_t n4 = (size_t)VOCAB * D_MODEL / 4;
        k_cvt_f16<<<(unsigned)((n4 + 255) / 256), 256>>>(emb, pEmbF, n4);
    }
    gemm_f16<<<dim3(OUTROWS / 128, VOCAB / 128), 256, 2 * STG_F>>>(
        pFinF, pEmbF, out, OUTROWS, VOCAB, D_MODEL);
}

// round 10
// speedup vs baseline: 1.0536x; 1.0462x over previous
#include <cuda_runtime.h>
#include <cuda_bf16.h>
#include <cuda_fp16.h>
#include <math.h>
#include <stdint.h>

#define D_MODEL 2048
#define D_STATE 32
#define HEADDIM 128
#define NHEADS 16
#define D_CONVK 4
#define M_PREFIX 8
#define MAX_LOOPS 6
#define BRIDGE_RANK 64
#define VOCAB 50432
#define LORA_RANK 4
#define BSZ 2
#define TLEN 512
#define TE (M_PREFIX + TLEN)     /* 520 */
#define ROWS (BSZ * TE)          /* 1040 */
#define DIN (2*D_MODEL + 2*D_STATE + NHEADS)  /* 4176 */
#define CONV_CH (D_MODEL + 2*D_STATE)         /* 2112 */
#define OUTROWS (BSZ * TLEN)     /* 1024 */
#define NSEQ (BSZ * NHEADS)      /* 32 */
#define NCH 13
#define CHL 40                   /* NCH * CHL == TE */

// ---------------- scratch (static device globals; no allocs) ----------------
__device__ float g_xe[ROWS * D_MODEL];
__device__ float g_xp[OUTROWS * D_MODEL];
__device__ float g_zx[ROWS * DIN];
__device__ float g_xbc[ROWS * CONV_CH];
__device__ float g_dt[ROWS * NHEADS];
__device__ float g_dA[ROWS * NHEADS];
__device__ float g_y[ROWS * D_MODEL];
__device__ float g_mo[ROWS * D_MODEL];
__device__ float g_t1[ROWS * BRIDGE_RANK];
// chunked-scan state (g_hs holds per-chunk LOCAL end states)
__device__ float g_hs[(size_t)NSEQ * NCH * HEADDIM * D_STATE];
__device__ float g_pa[NSEQ * NCH];
__device__ float g_cum[NSEQ * TE];

// bf16 hi/lo operand buffers (Win GEMM)
__device__ __nv_bfloat16 g_WinH[DIN * D_MODEL],   g_WinL[DIN * D_MODEL];
__device__ __nv_bfloat16 g_actH[ROWS * D_MODEL],  g_actL[ROWS * D_MODEL];
// fp16 operand buffers (Wout GEMM + logits GEMM, single-pass)
__device__ __half g_WoutF[D_MODEL * D_MODEL];
__device__ __half g_actF[ROWS * D_MODEL];
__device__ __half g_embF[(size_t)VOCAB * D_MODEL];
__device__ __half g_finF[OUTROWS * D_MODEL];

__device__ __forceinline__ float siluf(float x) { return x / (1.0f + expf(-x)); }

__device__ __forceinline__ uint32_t smem_u32(const void* p) {
    uint32_t a;
    asm("{ .reg .u64 t; cvta.to.shared.u64 t, %1; cvt.u32.u64 %0, t; }" : "=r"(a) : "l"(p));
    return a;
}
__device__ __forceinline__ void cpa16(uint32_t dst, const void* src, uint32_t bytes) {
    asm volatile("cp.async.cg.shared.global [%0], [%1], 16, %2;" :: "r"(dst), "l"(src), "r"(bytes));
}
__device__ __forceinline__ void split1(float v, __nv_bfloat16* hi, __nv_bfloat16* lo, size_t i) {
    __nv_bfloat16 h = __float2bfloat16(v);
    hi[i] = h;
    lo[i] = __float2bfloat16(v - __bfloat162float(h));
}

// ================= shared GEMM tile constants =================
#define KC 32
#define SROW 40
#define AB128 (128 * SROW * 2)      /* 10240 bytes per array */
#define STG_BF (4 * AB128)          /* bf3: AH AL BH BL */
#define STG_F  (2 * AB128)          /* f16: A B */

#define LDSM4(r, addr) \
    asm volatile("ldmatrix.sync.aligned.m8n8.x4.shared.b16 {%0,%1,%2,%3}, [%4];" \
        : "=r"((r)[0]), "=r"((r)[1]), "=r"((r)[2]), "=r"((r)[3]) : "r"(addr))

#define MMA_BF(d, a, b0, b1) \
    asm volatile("mma.sync.aligned.m16n8k16.row.col.f32.bf16.bf16.f32 " \
        "{%0,%1,%2,%3},{%4,%5,%6,%7},{%8,%9},{%0,%1,%2,%3};" \
        : "+f"((d)[0]), "+f"((d)[1]), "+f"((d)[2]), "+f"((d)[3]) \
        : "r"((a)[0]), "r"((a)[1]), "r"((a)[2]), "r"((a)[3]), "r"(b0), "r"(b1))

#define MMA_F16(d, a, b0, b1) \
    asm volatile("mma.sync.aligned.m16n8k16.row.col.f32.f16.f16.f32 " \
        "{%0,%1,%2,%3},{%4,%5,%6,%7},{%8,%9},{%0,%1,%2,%3};" \
        : "+f"((d)[0]), "+f"((d)[1]), "+f"((d)[2]), "+f"((d)[3]) \
        : "r"((a)[0]), "r"((a)[1]), "r"((a)[2]), "r"((a)[3]), "r"(b0), "r"(b1))

// ---- epilogue: warp-m rows = MT*16*2; bf3 uses MT=4 (wm 0..1), f16 uses MT=2 (wm 0..3) ----
template<int MT>
__device__ __forceinline__ void epi_store(float acc[MT][4][4], float* C,
        int m0, int n0, int M, int N, int wm, int wn, int lane) {
#pragma unroll
    for (int mt = 0; mt < MT; mt++) {
#pragma unroll
        for (int nt = 0; nt < 4; nt++) {
            int m = m0 + wm * (MT * 16) + mt * 16 + (lane >> 2);
            int n = n0 + wn * 32 + nt * 8 + (lane & 3) * 2;
            if (n < N) {
                if (m < M) {
                    float2 v = make_float2(acc[mt][nt][0], acc[mt][nt][1]);
                    *(float2*)(C + (size_t)m * N + n) = v;
                }
                if (m + 8 < M) {
                    float2 v = make_float2(acc[mt][nt][2], acc[mt][nt][3]);
                    *(float2*)(C + (size_t)(m + 8) * N + n) = v;
                }
            }
        }
    }
}

// ================= bf16x3 GEMM (Win): C = A @ B^T, TM=128, 256 thr =================
__device__ __forceinline__ void load_stage4(uint32_t sbase,
        const __nv_bfloat16* AH, const __nv_bfloat16* AL,
        const __nv_bfloat16* BH, const __nv_bfloat16* BL,
        int m0, int n0, int k0, int M, int N, int K, int tid) {
#pragma unroll
    for (int i = 0; i < 8; i++) {
        int idx = tid + (i << 8);
        int arr = idx >> 9;           // 0:AH 1:AL 2:BH 3:BL
        int c = idx & 511;
        int row = c >> 2, col = c & 3;
        uint32_t dst = sbase + (uint32_t)arr * AB128 + (uint32_t)(row * 80 + col * 16);
        const __nv_bfloat16* base;
        int g;
        uint32_t bytes = 16;
        if (arr < 2) {
            base = (arr == 0) ? AH : AL;
            g = m0 + row;
            if (g >= M) { g = 0; bytes = 0; }
        } else {
            base = (arr == 2) ? BH : BL;
            g = n0 + row;
            if (g >= N) { g = 0; bytes = 0; }
        }
        cpa16(dst, base + (size_t)g * K + k0 + col * 8, bytes);
    }
}

__global__ void __launch_bounds__(256, 2) gemm_bf3(
        const __nv_bfloat16* __restrict__ AH, const __nv_bfloat16* __restrict__ AL,
        const __nv_bfloat16* __restrict__ BH, const __nv_bfloat16* __restrict__ BL,
        float* __restrict__ C, int M, int N, int K) {
    extern __shared__ __align__(16) char smdyn[];
    uint32_t sb = smem_u32(smdyn);

    int tid = threadIdx.x, lane = tid & 31, wid = tid >> 5;
    int wm = wid >> 2, wn = wid & 3;
    int m0 = blockIdx.x * 128, n0 = blockIdx.y * 128;

    float acc[4][4][4] = {};

    uint32_t aRow = (uint32_t)(wm * 64 + (lane & 15));
    uint32_t aColB = (uint32_t)((lane >> 4) * 8) * 2;
    uint32_t bRow = (uint32_t)(wn * 32 + ((lane >> 4) & 1) * 8 + (lane & 7));
    uint32_t bColB = (uint32_t)(((lane >> 3) & 1) * 8) * 2;

    const int nch = K >> 5;
    load_stage4(sb, AH, AL, BH, BL, m0, n0, 0, M, N, K, tid);
    asm volatile("cp.async.commit_group;" ::: "memory");
    for (int ch = 0; ch < nch; ch++) {
        asm volatile("cp.async.wait_group 0;" ::: "memory");
        __syncthreads();
        uint32_t uS = sb + (uint32_t)((ch & 1) * STG_BF);
        if (ch + 1 < nch)
            load_stage4(sb + (uint32_t)(((ch + 1) & 1) * STG_BF), AH, AL, BH, BL,
                        m0, n0, (ch + 1) * KC, M, N, K, tid);
        asm volatile("cp.async.commit_group;" ::: "memory");
        uint32_t uAH = uS, uAL = uS + AB128, uBH = uS + 2*AB128, uBL = uS + 3*AB128;
#pragma unroll
        for (int ks = 0; ks < 2; ks++) {
            uint32_t kcb = (uint32_t)(ks * 16) * 2;
            uint32_t a[4][4], b[2][4];
            // pass 1: Ah * Bh
#pragma unroll
            for (int mt = 0; mt < 4; mt++)
                LDSM4(a[mt], uAH + ((aRow + mt * 16) * SROW) * 2 + kcb + aColB);
#pragma unroll
            for (int bt = 0; bt < 2; bt++)
                LDSM4(b[bt], uBH + ((bRow + bt * 16) * SROW) * 2 + kcb + bColB);
#pragma unroll
            for (int mt = 0; mt < 4; mt++)
#pragma unroll
                for (int nt = 0; nt < 4; nt++)
                    MMA_BF(acc[mt][nt], a[mt], b[nt >> 1][(nt & 1) * 2], b[nt >> 1][(nt & 1) * 2 + 1]);
            // pass 2: Ah * Bl (reuse a)
#pragma unroll
            for (int bt = 0; bt < 2; bt++)
                LDSM4(b[bt], uBL + ((bRow + bt * 16) * SROW) * 2 + kcb + bColB);
#pragma unroll
            for (int mt = 0; mt < 4; mt++)
#pragma unroll
                for (int nt = 0; nt < 4; nt++)
                    MMA_BF(acc[mt][nt], a[mt], b[nt >> 1][(nt & 1) * 2], b[nt >> 1][(nt & 1) * 2 + 1]);
            // pass 3: Al * Bh (reload both)
#pragma unroll
            for (int mt = 0; mt < 4; mt++)
                LDSM4(a[mt], uAL + ((aRow + mt * 16) * SROW) * 2 + kcb + aColB);
#pragma unroll
            for (int bt = 0; bt < 2; bt++)
                LDSM4(b[bt], uBH + ((bRow + bt * 16) * SROW) * 2 + kcb + bColB);
#pragma unroll
            for (int mt = 0; mt < 4; mt++)
#pragma unroll
                for (int nt = 0; nt < 4; nt++)
                    MMA_BF(acc[mt][nt], a[mt], b[nt >> 1][(nt & 1) * 2], b[nt >> 1][(nt & 1) * 2 + 1]);
        }
    }
    epi_store<4>(acc, C, m0, n0, M, N, wm, wn, lane);
}

// ================= fp16 GEMM (Wout + logits): 512 thr, warp tile 32x32 =================
// 16 warps (4x4 grid) -> 8 warps/SMSP at 2 CTAs/SM: double the eligible warps
// to cover LDSM->MMA dependency latency. acc[2][4][4]=32 regs -> ~60 regs total.
__global__ void __launch_bounds__(512, 2) gemm_f16(
        const __half* __restrict__ A, const __half* __restrict__ B,
        float* __restrict__ C, int M, int N, int K) {
    extern __shared__ __align__(16) char smdyn[];
    uint32_t sb = smem_u32(smdyn);

    int tid = threadIdx.x, lane = tid & 31, wid = tid >> 5;   // wid 0..15
    int wm = wid >> 2, wn = wid & 3;                          // 4 x 4 warp grid
    int m0 = blockIdx.x * 128, n0 = blockIdx.y * 128;

    float acc[2][4][4] = {};

    uint32_t aRow = (uint32_t)(wm * 32 + (lane & 15));
    uint32_t aColB = (uint32_t)((lane >> 4) * 8) * 2;
    uint32_t bRow = (uint32_t)(wn * 32 + ((lane >> 4) & 1) * 8 + (lane & 7));
    uint32_t bColB = (uint32_t)(((lane >> 3) & 1) * 8) * 2;

    const int nch = K >> 5;
    // loads: 2 arrays x 512 chunks of 16B; 512 threads x 2 iterations
    auto issue_loads = [&](uint32_t stagebase, int k0) {
#pragma unroll
        for (int i = 0; i < 2; i++) {
            int idx = tid + (i << 9);
            int c = idx & 511;
            int row = c >> 2, col = c & 3;
            const __half* base = (i == 0) ? A : B;
            int g = ((i == 0) ? m0 : n0) + row;
            int lim = (i == 0) ? M : N;
            uint32_t bytes = 16;
            if (g >= lim) { g = 0; bytes = 0; }
            cpa16(stagebase + (uint32_t)(i * AB128 + row * 80 + col * 16),
                  base + (size_t)g * K + k0 + col * 8, bytes);
        }
    };

    issue_loads(sb, 0);
    asm volatile("cp.async.commit_group;" ::: "memory");
    for (int ch = 0; ch < nch; ch++) {
        asm volatile("cp.async.wait_group 0;" ::: "memory");
        __syncthreads();
        uint32_t uS = sb + (uint32_t)((ch & 1) * STG_F);
        if (ch + 1 < nch)
            issue_loads(sb + (uint32_t)(((ch + 1) & 1) * STG_F), (ch + 1) * KC);
        asm volatile("cp.async.commit_group;" ::: "memory");
        uint32_t uA = uS, uB = uS + AB128;
#pragma unroll
        for (int ks = 0; ks < 2; ks++) {
            uint32_t kcb = (uint32_t)(ks * 16) * 2;
            uint32_t a[2][4], b[2][4];
#pragma unroll
            for (int mt = 0; mt < 2; mt++)
                LDSM4(a[mt], uA + ((aRow + mt * 16) * SROW) * 2 + kcb + aColB);
#pragma unroll
            for (int bt = 0; bt < 2; bt++)
                LDSM4(b[bt], uB + ((bRow + bt * 16) * SROW) * 2 + kcb + bColB);
#pragma unroll
            for (int mt = 0; mt < 2; mt++)
#pragma unroll
                for (int nt = 0; nt < 4; nt++)
                    MMA_F16(acc[mt][nt], a[mt], b[nt >> 1][(nt & 1) * 2], b[nt >> 1][(nt & 1) * 2 + 1]);
        }
    }
    epi_store<2>(acc, C, m0, n0, M, N, wm, wn, lane);
}

// ---------------- fused LoRA fold: Win -> bf16 hi/lo, Wout -> fp16 ----------------
__global__ void k_lora2(const float* __restrict__ in_base, const float* __restrict__ in_A,
                        const float* __restrict__ in_B,
                        const float* __restrict__ out_base, const float* __restrict__ out_A,
                        const float* __restrict__ out_B) {
    int i = blockIdx.x * 256 + threadIdx.x;
    const int T1 = DIN * D_MODEL;
    if (i < T1) {
        int r = i / D_MODEL, c = i % D_MODEL;
        float s = 0.f;
#pragma unroll
        for (int q = 0; q < LORA_RANK; q++) s += in_B[r*LORA_RANK + q] * in_A[q*D_MODEL + c];
        split1(in_base[i] + 2.0f * s, g_WinH, g_WinL, i);
    } else {
        int j = i - T1;
        if (j >= D_MODEL * D_MODEL) return;
        int r = j / D_MODEL, c = j % D_MODEL;
        float s = 0.f;
#pragma unroll
        for (int q = 0; q < LORA_RANK; q++) s += out_B[r*LORA_RANK + q] * out_A[q*D_MODEL + c];
        g_WoutF[j] = __float2half(out_base[j] + 2.0f * s);
    }
}

// ---------------- f32 -> fp16 convert (vectorized), for emb ----------------
__global__ void k_cvt_f16(const float* __restrict__ in, __half* __restrict__ o, size_t n4) {
    size_t i = (size_t)blockIdx.x * 256 + threadIdx.x;
    if (i >= n4) return;
    float4 v = *(const float4*)(in + i * 4);
    __half2 p0 = __floats2half2_rn(v.x, v.y);
    __half2 p1 = __floats2half2_rn(v.z, v.w);
    uint2 pk;
    pk.x = *(uint32_t*)&p0;
    pk.y = *(uint32_t*)&p1;
    *(uint2*)(o + i * 4) = pk;
}

// ---------------- embedding gather + latent prefix ----------------
__global__ void k_embed(const int* __restrict__ ids, const float* __restrict__ emb,
                        const float* __restrict__ latent) {
    int i = blockIdx.x * 256 + threadIdx.x;
    if (i >= ROWS * D_MODEL) return;
    int row = i / D_MODEL, c = i % D_MODEL;
    int b = row / TE, t = row % TE;
    float v;
    if (t < M_PREFIX) {
        v = latent[t * D_MODEL + c];
    } else {
        int tok = ids[b * TLEN + (t - M_PREFIX)];
        v = emb[(size_t)tok * D_MODEL + c];
        g_xp[(b * TLEN + (t - M_PREFIX)) * D_MODEL + c] = v;
    }
    g_xe[i] = v;
}

// ---------------- lifeline + RoPE; emits f32 residual + bf16 hi/lo ----------------
__global__ void k_prerope(const float* __restrict__ gate, float loop_i) {
    int row = blockIdx.x;
    int j = threadIdx.x;              // pair index 0..1023
    int b = row / TE, t = row % TE;
    float v0 = g_xe[row * D_MODEL + 2*j];
    float v1 = g_xe[row * D_MODEL + 2*j + 1];
    if (t >= M_PREFIX) {
        int pr = (b * TLEN + t - M_PREFIX) * D_MODEL;
        v0 += gate[2*j]     * g_xp[pr + 2*j];
        v1 += gate[2*j + 1] * g_xp[pr + 2*j + 1];
    }
    float freq = loop_i * powf(10000.0f, -(float)(2*j) / (float)D_MODEL);
    float s, c;
    sincosf(freq, &s, &c);
    float r0 = v0 * c - v1 * s;
    float r1 = v1 * c + v0 * s;
    size_t o = (size_t)row * D_MODEL + 2*j;
    g_xe[o] = r0; g_xe[o + 1] = r1;
    split1(r0, g_actH, g_actL, o);
    split1(r1, g_actH, g_actL, o + 1);
}

// ---------------- conv (K=4) + bias + silu, fused with dt/dA ----------------
__global__ void k_conv(const float* __restrict__ cw, const float* __restrict__ cb,
                       const float* __restrict__ dt_bias, const float* __restrict__ A_log) {
    int i = blockIdx.x * 256 + threadIdx.x;
    if (i < ROWS * NHEADS) {
        int row = i / NHEADS, h = i % NHEADS;
        float x = g_zx[(size_t)row * DIN + (2*D_MODEL + 2*D_STATE) + h] + dt_bias[h];
        float sp = (x > 20.f) ? x : log1pf(expf(x));
        g_dt[i] = sp;
        g_dA[i] = expf(-expf(A_log[h]) * sp);
    }
    if (i >= ROWS * CONV_CH) return;
    int row = i / CONV_CH, c = i % CONV_CH;
    int b = row / TE, t = row % TE;
    float acc = cb[c];
#pragma unroll
    for (int k = 0; k < D_CONVK; k++) {
        int tt = t - (D_CONVK - 1) + k;
        if (tt >= 0) acc += g_zx[((size_t)(b*TE + tt)) * DIN + D_MODEL + c] * cw[c*D_CONVK + k];
    }
    g_xbc[i] = siluf(acc);
}

// ---------------- chunked scan phase 1: local scan per (seq, chunk) ----------------
__global__ void k_scan_local(const float* __restrict__ D_skip) {
    int sc = blockIdx.x;               // seq * NCH + c
    int seq = sc / NCH, c = sc % NCH;
    int b = seq >> 4, h = seq & 15;
    int p = threadIdx.x;
    int t0 = c * CHL;
    float hs[D_STATE];
#pragma unroll
    for (int n = 0; n < D_STATE; n++) hs[n] = 0.f;
    __shared__ float sB[2][D_STATE], sC[2][D_STATE];
    float Dh = D_skip[h];
    float cum = 1.f;

    const float* row0 = g_xbc + (size_t)(b*TE + t0) * CONV_CH;
    if (p < 2*D_STATE) {
        float v = row0[D_MODEL + p];
        if (p < D_STATE) sB[0][p] = v; else sC[0][p - D_STATE] = v;
    }
    float x   = row0[h * HEADDIM + p];
    float dAv = g_dA[(size_t)(b*TE + t0) * NHEADS + h];
    float dtv = g_dt[(size_t)(b*TE + t0) * NHEADS + h];
    __syncthreads();

    for (int tt = 0; tt < CHL; tt++) {
        int t = t0 + tt;
        int tn = (tt + 1 < CHL) ? t + 1 : t;
        size_t rn = (size_t)(b*TE + tn);
        const float* rown = g_xbc + rn * CONV_CH;
        float xn   = rown[h * HEADDIM + p];
        float dAn  = g_dA[rn * NHEADS + h];
        float dtn  = g_dt[rn * NHEADS + h];
        int nxt = (tt + 1) & 1, cur = tt & 1;
        if (p < 2*D_STATE) {
            float v = rown[D_MODEL + p];
            if (p < D_STATE) sB[nxt][p] = v; else sC[nxt][p - D_STATE] = v;
        }
        cum *= dAv;
        float coef = dtv * x;
        float a0 = 0.f, a1 = 0.f, a2 = 0.f, a3 = 0.f;
#pragma unroll
        for (int n = 0; n < D_STATE; n += 4) {
            hs[n+0] = dAv * hs[n+0] + coef * sB[cur][n+0]; a0 += hs[n+0] * sC[cur][n+0];
            hs[n+1] = dAv * hs[n+1] + coef * sB[cur][n+1]; a1 += hs[n+1] * sC[cur][n+1];
            hs[n+2] = dAv * hs[n+2] + coef * sB[cur][n+2]; a2 += hs[n+2] * sC[cur][n+2];
            hs[n+3] = dAv * hs[n+3] + coef * sB[cur][n+3]; a3 += hs[n+3] * sC[cur][n+3];
        }
        g_y[(size_t)(b*TE + t) * D_MODEL + h * HEADDIM + p] = (a0 + a1) + (a2 + a3) + Dh * x;
        if (p == 0) g_cum[seq * TE + t] = cum;
        __syncthreads();
        x = xn; dAv = dAn; dtv = dtn;
    }
    size_t hbase = (size_t)sc * (HEADDIM * D_STATE) + (size_t)p * D_STATE;
#pragma unroll
    for (int n = 0; n < D_STATE; n++) g_hs[hbase + n] = hs[n];
    if (p == 0) g_pa[sc] = cum;
}

// ---------------- chunked scan phase 2+3 fused: inline h_start prefix, then fixup ----------------
__global__ void k_scan_fix() {
    int sc = blockIdx.x;
    int seq = sc / NCH, c = sc % NCH;
    if (c == 0) return;                // h_start is zero
    int b = seq >> 4, h = seq & 15;
    int p = threadIdx.x;
    int t0 = c * CHL;
    __shared__ float sC[CHL][D_STATE + 1];
    __shared__ float scum[CHL];
    for (int i = p; i < CHL * D_STATE; i += HEADDIM) {
        int tt = i / D_STATE, n = i % D_STATE;
        sC[tt][n] = g_xbc[(size_t)(b*TE + t0 + tt) * CONV_CH + D_MODEL + D_STATE + n];
    }
    if (p < CHL) scum[p] = g_cum[seq * TE + t0 + p];
    // inline combine: h_start = scan over chunks 0..c-1 of local ends
    float hrow[D_STATE];
#pragma unroll
    for (int n = 0; n < D_STATE; n++) hrow[n] = 0.f;
    for (int c2 = 0; c2 < c; c2++) {
        float pa = g_pa[seq * NCH + c2];
        size_t hb = (size_t)(seq * NCH + c2) * (HEADDIM * D_STATE) + (size_t)p * D_STATE;
#pragma unroll
        for (int n = 0; n < D_STATE; n++)
            hrow[n] = pa * hrow[n] + g_hs[hb + n];
    }
    __syncthreads();
#pragma unroll 4
    for (int tt = 0; tt < CHL; tt++) {
        float d0 = 0.f, d1 = 0.f;
#pragma unroll
        for (int n = 0; n < D_STATE; n += 2) {
            d0 += hrow[n]   * sC[tt][n];
            d1 += hrow[n+1] * sC[tt][n+1];
        }
        size_t yi = (size_t)(b*TE + t0 + tt) * D_MODEL + h * HEADDIM + p;
        g_y[yi] += scum[tt] * (d0 + d1);
    }
}

// ---------------- y * silu(z), rmsnorm -> fp16 (Wout GEMM A) ----------------
__global__ void k_gatenorm(const float* __restrict__ w) {
    int row = blockIdx.x;
    const float* yr = g_y + (size_t)row * D_MODEL;
    const float* zr = g_zx + (size_t)row * DIN;
    float vals[8];
    float ss = 0.f;
#pragma unroll
    for (int q = 0; q < 8; q++) {
        int j = threadIdx.x + q * 256;
        float z = zr[j];
        float v = yr[j] * siluf(z);
        vals[q] = v; ss += v * v;
    }
    __shared__ float sred[8];
    for (int o = 16; o > 0; o >>= 1) ss += __shfl_down_sync(0xffffffffu, ss, o);
    if ((threadIdx.x & 31) == 0) sred[threadIdx.x >> 5] = ss;
    __syncthreads();
    if (threadIdx.x < 8) {
        float t = sred[threadIdx.x];
        t += __shfl_down_sync(0xffu, t, 4);
        t += __shfl_down_sync(0xffu, t, 2);
        t += __shfl_down_sync(0xffu, t, 1);
        if (threadIdx.x == 0) sred[0] = t;
    }
    __syncthreads();
    float scale = rsqrtf(sred[0] / (float)D_MODEL + 1e-6f);
#pragma unroll
    for (int q = 0; q < 8; q++) {
        int j = threadIdx.x + q * 256;
        g_actF[(size_t)row * D_MODEL + j] = __float2half(vals[q] * scale * w[j]);
    }
}

// ---------------- xe = rmsnorm(xe + mamba_out, loop_norm_w) in place ----------------
__global__ void k_addnorm(const float* __restrict__ w) {
    int row = blockIdx.x;
    float vals[8];
    float ss = 0.f;
#pragma unroll
    for (int q = 0; q < 8; q++) {
        int j = threadIdx.x + q * 256;
        float v = g_xe[(size_t)row * D_MODEL + j] + g_mo[(size_t)row * D_MODEL + j];
        vals[q] = v; ss += v * v;
    }
    __shared__ float sred[8];
    for (int o = 16; o > 0; o >>= 1) ss += __shfl_down_sync(0xffffffffu, ss, o);
    if ((threadIdx.x & 31) == 0) sred[threadIdx.x >> 5] = ss;
    __syncthreads();
    if (threadIdx.x < 8) {
        float t = sred[threadIdx.x];
        t += __shfl_down_sync(0xffu, t, 4);
        t += __shfl_down_sync(0xffu, t, 2);
        t += __shfl_down_sync(0xffu, t, 1);
        if (threadIdx.x == 0) sred[0] = t;
    }
    __syncthreads();
    float scale = rsqrtf(sred[0] / (float)D_MODEL + 1e-6f);
#pragma unroll
    for (int q = 0; q < 8; q++) {
        int j = threadIdx.x + q * 256;
        g_xe[(size_t)row * D_MODEL + j] = vals[q] * scale * w[j];
    }
}

// ---------------- bridge down: t1 = xe @ down^T (rank 64) ----------------
__global__ void k_bridge_down(const float* __restrict__ down) {
    int m = blockIdx.x;
    int r = threadIdx.x >> 2;
    int part = threadIdx.x & 3;
    const float* xr = g_xe + (size_t)m * D_MODEL;
    const float* dr = down + r * D_MODEL;
    float acc = 0.f;
    int k0 = part * 512;
    for (int k = k0; k < k0 + 512; k++) acc += xr[k] * dr[k];
    acc += __shfl_down_sync(0xffffffffu, acc, 1);
    acc += __shfl_down_sync(0xffffffffu, acc, 2);
    if (part == 0) g_t1[m * BRIDGE_RANK + r] = acc;
}

// ---------------- bridge up + residual + extract -> fp16 (logits A) ----------------
__global__ void k_bridge_up(const float* __restrict__ up) {
    int ro = blockIdx.x;
    int jc = blockIdx.y;
    int b = ro >> 9, t = M_PREFIX + (ro & 511);
    int m = b * TE + t;
    __shared__ float s1[BRIDGE_RANK];
    if (threadIdx.x < BRIDGE_RANK) s1[threadIdx.x] = g_t1[m * BRIDGE_RANK + threadIdx.x];
    __syncthreads();
    int j = jc * 256 + threadIdx.x;
    float acc = g_xe[(size_t)m * D_MODEL + j];
#pragma unroll
    for (int r = 0; r < BRIDGE_RANK; r++) acc += s1[r] * up[j * BRIDGE_RANK + r];
    g_finF[(size_t)ro * D_MODEL + j] = __float2half(acc);
}

// ---------------- launch ----------------
extern "C" void kernel_launch(void* const* d_in, const int* in_sizes, int n_in,
                              void* d_out, int out_size) {
    const int*   ids         = (const int*)  d_in[0];
    const float* emb         = (const float*)d_in[1];
    const float* latent      = (const float*)d_in[2];
    const float* gate        = (const float*)d_in[3];
    const float* loop_norm_w = (const float*)d_in[4];
    const float* in_base     = (const float*)d_in[5];
    const float* in_A        = (const float*)d_in[6];
    const float* in_B        = (const float*)d_in[7];
    const float* conv_w      = (const float*)d_in[8];
    const float* conv_b      = (const float*)d_in[9];
    const float* dt_bias     = (const float*)d_in[10];
    const float* A_log       = (const float*)d_in[11];
    const float* D_skip      = (const float*)d_in[12];
    const float* ssm_norm_w  = (const float*)d_in[13];
    const float* out_base    = (const float*)d_in[14];
    const float* out_A       = (const float*)d_in[15];
    const float* out_B       = (const float*)d_in[16];
    const float* bridge_down = (const float*)d_in[17];
    const float* bridge_up   = (const float*)d_in[18];
    float* out = (float*)d_out;

    float *pZx, *pMo;
    __nv_bfloat16 *pWinH, *pWinL, *pActH, *pActL;
    __half *pWoutF, *pActF, *pEmbF, *pFinF;
    cudaGetSymbolAddress((void**)&pZx,    g_zx);
    cudaGetSymbolAddress((void**)&pMo,    g_mo);
    cudaGetSymbolAddress((void**)&pWinH,  g_WinH);
    cudaGetSymbolAddress((void**)&pWinL,  g_WinL);
    cudaGetSymbolAddress((void**)&pActH,  g_actH);
    cudaGetSymbolAddress((void**)&pActL,  g_actL);
    cudaGetSymbolAddress((void**)&pWoutF, g_WoutF);
    cudaGetSymbolAddress((void**)&pActF,  g_actF);
    cudaGetSymbolAddress((void**)&pEmbF,  g_embF);
    cudaGetSymbolAddress((void**)&pFinF,  g_finF);

    cudaFuncSetAttribute(gemm_bf3, cudaFuncAttributeMaxDynamicSharedMemorySize, 2 * STG_BF);
    cudaFuncSetAttribute(gemm_f16, cudaFuncAttributeMaxDynamicSharedMemorySize, 2 * STG_F);

    k_lora2<<<((DIN + D_MODEL) * D_MODEL + 255) / 256, 256>>>(
        in_base, in_A, in_B, out_base, out_A, out_B);
    k_embed<<<(ROWS * D_MODEL + 255) / 256, 256>>>(ids, emb, latent);

    for (int li = 0; li < MAX_LOOPS; li++) {
        k_prerope<<<ROWS, 1024>>>(gate, (float)li);
        gemm_bf3<<<dim3((ROWS + 127) / 128, (DIN + 127) / 128), 256, 2 * STG_BF>>>(
            pActH, pActL, pWinH, pWinL, pZx, ROWS, DIN, D_MODEL);
        k_conv<<<(ROWS * CONV_CH + 255) / 256, 256>>>(conv_w, conv_b, dt_bias, A_log);
        k_scan_local<<<NSEQ * NCH, HEADDIM>>>(D_skip);
        k_scan_fix<<<NSEQ * NCH, HEADDIM>>>();
        k_gatenorm<<<ROWS, 256>>>(ssm_norm_w);
        gemm_f16<<<dim3((ROWS + 127) / 128, D_MODEL / 128), 512, 2 * STG_F>>>(
            pActF, pWoutF, pMo, ROWS, D_MODEL, D_MODEL);
        k_addnorm<<<ROWS, 256>>>(loop_norm_w);
    }

    k_bridge_down<<<ROWS, 256>>>(bridge_down);
    k_bridge_up<<<dim3(OUTROWS, D_MODEL / 256), 256>>>(bridge_up);
    {
        size_t n4 = (size_t)VOCAB * D_MODEL / 4;
        k_cvt_f16<<<(unsigned)((n4 + 255) / 256), 256>>>(emb, pEmbF, n4);
    }
    gemm_f16<<<dim3(OUTROWS / 128, VOCAB / 128), 512, 2 * STG_F>>>(
        pFinF, pEmbF, out, OUTROWS, VOCAB, D_MODEL);
}

// round 13
// speedup vs baseline: 1.0538x; 1.0001x over previous
#include <cuda_runtime.h>
#include <cuda_bf16.h>
#include <cuda_fp16.h>
#include <math.h>
#include <stdint.h>

#define D_MODEL 2048
#define D_STATE 32
#define HEADDIM 128
#define NHEADS 16
#define D_CONVK 4
#define M_PREFIX 8
#define MAX_LOOPS 6
#define BRIDGE_RANK 64
#define VOCAB 50432
#define LORA_RANK 4
#define BSZ 2
#define TLEN 512
#define TE (M_PREFIX + TLEN)     /* 520 */
#define ROWS (BSZ * TE)          /* 1040 */
#define DIN (2*D_MODEL + 2*D_STATE + NHEADS)  /* 4176 */
#define CONV_CH (D_MODEL + 2*D_STATE)         /* 2112 */
#define OUTROWS (BSZ * TLEN)     /* 1024 */
#define NSEQ (BSZ * NHEADS)      /* 32 */
#define NCH 13
#define CHL 40                   /* NCH * CHL == TE */

// ---------------- scratch (static device globals; no allocs) ----------------
__device__ float g_xe[ROWS * D_MODEL];
__device__ float g_xp[OUTROWS * D_MODEL];
__device__ float g_zx[ROWS * DIN];
__device__ float g_xbc[ROWS * CONV_CH];
__device__ float g_dt[ROWS * NHEADS];
__device__ float g_dA[ROWS * NHEADS];
__device__ float g_y[ROWS * D_MODEL];
__device__ float g_mo[ROWS * D_MODEL];
__device__ float g_t1[ROWS * BRIDGE_RANK];
// chunked-scan state (g_hs holds per-chunk LOCAL end states)
__device__ float g_hs[(size_t)NSEQ * NCH * HEADDIM * D_STATE];
__device__ float g_pa[NSEQ * NCH];
__device__ float g_cum[NSEQ * TE];

// bf16 hi/lo operand buffers (Win GEMM)
__device__ __nv_bfloat16 g_WinH[DIN * D_MODEL],   g_WinL[DIN * D_MODEL];
__device__ __nv_bfloat16 g_actH[ROWS * D_MODEL],  g_actL[ROWS * D_MODEL];
// fp16 operand buffers (Wout GEMM + logits GEMM, single-pass)
__device__ __half g_WoutF[D_MODEL * D_MODEL];
__device__ __half g_actF[ROWS * D_MODEL];
__device__ __half g_embF[(size_t)VOCAB * D_MODEL];
__device__ __half g_finF[OUTROWS * D_MODEL];

__device__ __forceinline__ float siluf(float x) { return x / (1.0f + expf(-x)); }

__device__ __forceinline__ uint32_t smem_u32(const void* p) {
    uint32_t a;
    asm("{ .reg .u64 t; cvta.to.shared.u64 t, %1; cvt.u32.u64 %0, t; }" : "=r"(a) : "l"(p));
    return a;
}
__device__ __forceinline__ void cpa16(uint32_t dst, const void* src, uint32_t bytes) {
    asm volatile("cp.async.cg.shared.global [%0], [%1], 16, %2;" :: "r"(dst), "l"(src), "r"(bytes));
}
__device__ __forceinline__ void split1(float v, __nv_bfloat16* hi, __nv_bfloat16* lo, size_t i) {
    __nv_bfloat16 h = __float2bfloat16(v);
    hi[i] = h;
    lo[i] = __float2bfloat16(v - __bfloat162float(h));
}

// ================= shared GEMM tile constants =================
#define KC 32
#define SROW 40
#define AB128 (128 * SROW * 2)      /* 10240 bytes per array */
#define STG_BF (4 * AB128)          /* bf3: AH AL BH BL */
#define STG_F  (2 * AB128)          /* f16: A B */

#define LDSM4(r, addr) \
    asm volatile("ldmatrix.sync.aligned.m8n8.x4.shared.b16 {%0,%1,%2,%3}, [%4];" \
        : "=r"((r)[0]), "=r"((r)[1]), "=r"((r)[2]), "=r"((r)[3]) : "r"(addr))

#define MMA_BF(d, a, b0, b1) \
    asm volatile("mma.sync.aligned.m16n8k16.row.col.f32.bf16.bf16.f32 " \
        "{%0,%1,%2,%3},{%4,%5,%6,%7},{%8,%9},{%0,%1,%2,%3};" \
        : "+f"((d)[0]), "+f"((d)[1]), "+f"((d)[2]), "+f"((d)[3]) \
        : "r"((a)[0]), "r"((a)[1]), "r"((a)[2]), "r"((a)[3]), "r"(b0), "r"(b1))

#define MMA_F16(d, a, b0, b1) \
    asm volatile("mma.sync.aligned.m16n8k16.row.col.f32.f16.f16.f32 " \
        "{%0,%1,%2,%3},{%4,%5,%6,%7},{%8,%9},{%0,%1,%2,%3};" \
        : "+f"((d)[0]), "+f"((d)[1]), "+f"((d)[2]), "+f"((d)[3]) \
        : "r"((a)[0]), "r"((a)[1]), "r"((a)[2]), "r"((a)[3]), "r"(b0), "r"(b1))

// ---- epilogue: warp tile 32x32, 4x4 warp grid (both GEMMs, 512 thr) ----
__device__ __forceinline__ void epi_store2(float acc[2][4][4], float* C,
        int m0, int n0, int M, int N, int wm, int wn, int lane) {
#pragma unroll
    for (int mt = 0; mt < 2; mt++) {
#pragma unroll
        for (int nt = 0; nt < 4; nt++) {
            int m = m0 + wm * 32 + mt * 16 + (lane >> 2);
            int n = n0 + wn * 32 + nt * 8 + (lane & 3) * 2;
            if (n < N) {
                if (m < M) {
                    float2 v = make_float2(acc[mt][nt][0], acc[mt][nt][1]);
                    *(float2*)(C + (size_t)m * N + n) = v;
                }
                if (m + 8 < M) {
                    float2 v = make_float2(acc[mt][nt][2], acc[mt][nt][3]);
                    *(float2*)(C + (size_t)(m + 8) * N + n) = v;
                }
            }
        }
    }
}

// ================= bf16x3 GEMM (Win): C = A @ B^T, TM=128, 512 thr =================
// 16 warps (4x4), warp tile 32x32, acc 32 regs -> ~85 regs total -> 2 CTAs/SM,
// 8 warps/SMSP to cover LDSM->MMA dependency latency (same cure as gemm_f16 R10).
__global__ void __launch_bounds__(512, 2) gemm_bf3(
        const __nv_bfloat16* __restrict__ AH, const __nv_bfloat16* __restrict__ AL,
        const __nv_bfloat16* __restrict__ BH, const __nv_bfloat16* __restrict__ BL,
        float* __restrict__ C, int M, int N, int K) {
    extern __shared__ __align__(16) char smdyn[];
    uint32_t sb = smem_u32(smdyn);

    int tid = threadIdx.x, lane = tid & 31, wid = tid >> 5;   // wid 0..15
    int wm = wid >> 2, wn = wid & 3;                          // 4 x 4 warp grid
    int m0 = blockIdx.x * 128, n0 = blockIdx.y * 128;

    float acc[2][4][4] = {};

    const __nv_bfloat16* bases[4] = {AH, AL, BH, BL};
    // per-stage loads: 4 arrays x 512 16B-chunks; 512 threads x 4 iters, arr == i
    auto issue_loads = [&](uint32_t stagebase, int k0) {
#pragma unroll
        for (int i = 0; i < 4; i++) {
            int c = tid;                      // chunk within array
            int row = c >> 2, col = c & 3;
            int g = ((i < 2) ? m0 : n0) + row;
            int lim = (i < 2) ? M : N;
            uint32_t bytes = 16;
            if (g >= lim) { g = 0; bytes = 0; }
            cpa16(stagebase + (uint32_t)(i * AB128 + row * 80 + col * 16),
                  bases[i] + (size_t)g * K + k0 + col * 8, bytes);
        }
    };

    uint32_t aRow = (uint32_t)(wm * 32 + (lane & 15));
    uint32_t aColB = (uint32_t)((lane >> 4) * 8) * 2;
    uint32_t bRow = (uint32_t)(wn * 32 + ((lane >> 4) & 1) * 8 + (lane & 7));
    uint32_t bColB = (uint32_t)(((lane >> 3) & 1) * 8) * 2;

    const int nch = K >> 5;
    issue_loads(sb, 0);
    asm volatile("cp.async.commit_group;" ::: "memory");
    for (int ch = 0; ch < nch; ch++) {
        asm volatile("cp.async.wait_group 0;" ::: "memory");
        __syncthreads();
        uint32_t uS = sb + (uint32_t)((ch & 1) * STG_BF);
        if (ch + 1 < nch)
            issue_loads(sb + (uint32_t)(((ch + 1) & 1) * STG_BF), (ch + 1) * KC);
        asm volatile("cp.async.commit_group;" ::: "memory");
        uint32_t uAH = uS, uAL = uS + AB128, uBH = uS + 2*AB128, uBL = uS + 3*AB128;
#pragma unroll
        for (int ks = 0; ks < 2; ks++) {
            uint32_t kcb = (uint32_t)(ks * 16) * 2;
            uint32_t a[2][4], b[2][4];
            // pass 1: Ah * Bh
#pragma unroll
            for (int mt = 0; mt < 2; mt++)
                LDSM4(a[mt], uAH + ((aRow + mt * 16) * SROW) * 2 + kcb + aColB);
#pragma unroll
            for (int bt = 0; bt < 2; bt++)
                LDSM4(b[bt], uBH + ((bRow + bt * 16) * SROW) * 2 + kcb + bColB);
#pragma unroll
            for (int mt = 0; mt < 2; mt++)
#pragma unroll
                for (int nt = 0; nt < 4; nt++)
                    MMA_BF(acc[mt][nt], a[mt], b[nt >> 1][(nt & 1) * 2], b[nt >> 1][(nt & 1) * 2 + 1]);
            // pass 2: Ah * Bl (reuse a)
#pragma unroll
            for (int bt = 0; bt < 2; bt++)
                LDSM4(b[bt], uBL + ((bRow + bt * 16) * SROW) * 2 + kcb + bColB);
#pragma unroll
            for (int mt = 0; mt < 2; mt++)
#pragma unroll
                for (int nt = 0; nt < 4; nt++)
                    MMA_BF(acc[mt][nt], a[mt], b[nt >> 1][(nt & 1) * 2], b[nt >> 1][(nt & 1) * 2 + 1]);
            // pass 3: Al * Bh (reload both)
#pragma unroll
            for (int mt = 0; mt < 2; mt++)
                LDSM4(a[mt], uAL + ((aRow + mt * 16) * SROW) * 2 + kcb + aColB);
#pragma unroll
            for (int bt = 0; bt < 2; bt++)
                LDSM4(b[bt], uBH + ((bRow + bt * 16) * SROW) * 2 + kcb + bColB);
#pragma unroll
            for (int mt = 0; mt < 2; mt++)
#pragma unroll
                for (int nt = 0; nt < 4; nt++)
                    MMA_BF(acc[mt][nt], a[mt], b[nt >> 1][(nt & 1) * 2], b[nt >> 1][(nt & 1) * 2 + 1]);
        }
    }
    epi_store2(acc, C, m0, n0, M, N, wm, wn, lane);
}

// ================= fp16 GEMM (Wout + logits): 512 thr, warp tile 32x32 =================
__global__ void __launch_bounds__(512, 2) gemm_f16(
        const __half* __restrict__ A, const __half* __restrict__ B,
        float* __restrict__ C, int M, int N, int K) {
    extern __shared__ __align__(16) char smdyn[];
    uint32_t sb = smem_u32(smdyn);

    int tid = threadIdx.x, lane = tid & 31, wid = tid >> 5;   // wid 0..15
    int wm = wid >> 2, wn = wid & 3;                          // 4 x 4 warp grid
    int m0 = blockIdx.x * 128, n0 = blockIdx.y * 128;

    float acc[2][4][4] = {};

    uint32_t aRow = (uint32_t)(wm * 32 + (lane & 15));
    uint32_t aColB = (uint32_t)((lane >> 4) * 8) * 2;
    uint32_t bRow = (uint32_t)(wn * 32 + ((lane >> 4) & 1) * 8 + (lane & 7));
    uint32_t bColB = (uint32_t)(((lane >> 3) & 1) * 8) * 2;

    const int nch = K >> 5;
    auto issue_loads = [&](uint32_t stagebase, int k0) {
#pragma unroll
        for (int i = 0; i < 2; i++) {
            int c = tid;
            int row = c >> 2, col = c & 3;
            const __half* base = (i == 0) ? A : B;
            int g = ((i == 0) ? m0 : n0) + row;
            int lim = (i == 0) ? M : N;
            uint32_t bytes = 16;
            if (g >= lim) { g = 0; bytes = 0; }
            cpa16(stagebase + (uint32_t)(i * AB128 + row * 80 + col * 16),
                  base + (size_t)g * K + k0 + col * 8, bytes);
        }
    };

    issue_loads(sb, 0);
    asm volatile("cp.async.commit_group;" ::: "memory");
    for (int ch = 0; ch < nch; ch++) {
        asm volatile("cp.async.wait_group 0;" ::: "memory");
        __syncthreads();
        uint32_t uS = sb + (uint32_t)((ch & 1) * STG_F);
        if (ch + 1 < nch)
            issue_loads(sb + (uint32_t)(((ch + 1) & 1) * STG_F), (ch + 1) * KC);
        asm volatile("cp.async.commit_group;" ::: "memory");
        uint32_t uA = uS, uB = uS + AB128;
#pragma unroll
        for (int ks = 0; ks < 2; ks++) {
            uint32_t kcb = (uint32_t)(ks * 16) * 2;
            uint32_t a[2][4], b[2][4];
#pragma unroll
            for (int mt = 0; mt < 2; mt++)
                LDSM4(a[mt], uA + ((aRow + mt * 16) * SROW) * 2 + kcb + aColB);
#pragma unroll
            for (int bt = 0; bt < 2; bt++)
                LDSM4(b[bt], uB + ((bRow + bt * 16) * SROW) * 2 + kcb + bColB);
#pragma unroll
            for (int mt = 0; mt < 2; mt++)
#pragma unroll
                for (int nt = 0; nt < 4; nt++)
                    MMA_F16(acc[mt][nt], a[mt], b[nt >> 1][(nt & 1) * 2], b[nt >> 1][(nt & 1) * 2 + 1]);
        }
    }
    epi_store2(acc, C, m0, n0, M, N, wm, wn, lane);
}

// ---------------- fused LoRA fold: Win -> bf16 hi/lo, Wout -> fp16 ----------------
__global__ void k_lora2(const float* __restrict__ in_base, const float* __restrict__ in_A,
                        const float* __restrict__ in_B,
                        const float* __restrict__ out_base, const float* __restrict__ out_A,
                        const float* __restrict__ out_B) {
    int i = blockIdx.x * 256 + threadIdx.x;
    const int T1 = DIN * D_MODEL;
    if (i < T1) {
        int r = i / D_MODEL, c = i % D_MODEL;
        float s = 0.f;
#pragma unroll
        for (int q = 0; q < LORA_RANK; q++) s += in_B[r*LORA_RANK + q] * in_A[q*D_MODEL + c];
        split1(in_base[i] + 2.0f * s, g_WinH, g_WinL, i);
    } else {
        int j = i - T1;
        if (j >= D_MODEL * D_MODEL) return;
        int r = j / D_MODEL, c = j % D_MODEL;
        float s = 0.f;
#pragma unroll
        for (int q = 0; q < LORA_RANK; q++) s += out_B[r*LORA_RANK + q] * out_A[q*D_MODEL + c];
        g_WoutF[j] = __float2half(out_base[j] + 2.0f * s);
    }
}

// ---------------- f32 -> fp16 convert (vectorized), for emb ----------------
__global__ void k_cvt_f16(const float* __restrict__ in, __half* __restrict__ o, size_t n4) {
    size_t i = (size_t)blockIdx.x * 256 + threadIdx.x;
    if (i >= n4) return;
    float4 v = *(const float4*)(in + i * 4);
    __half2 p0 = __floats2half2_rn(v.x, v.y);
    __half2 p1 = __floats2half2_rn(v.z, v.w);
    uint2 pk;
    pk.x = *(uint32_t*)&p0;
    pk.y = *(uint32_t*)&p1;
    *(uint2*)(o + i * 4) = pk;
}

// ---------------- embedding gather + latent prefix ----------------
__global__ void k_embed(const int* __restrict__ ids, const float* __restrict__ emb,
                        const float* __restrict__ latent) {
    int i = blockIdx.x * 256 + threadIdx.x;
    if (i >= ROWS * D_MODEL) return;
    int row = i / D_MODEL, c = i % D_MODEL;
    int b = row / TE, t = row % TE;
    float v;
    if (t < M_PREFIX) {
        v = latent[t * D_MODEL + c];
    } else {
        int tok = ids[b * TLEN + (t - M_PREFIX)];
        v = emb[(size_t)tok * D_MODEL + c];
        g_xp[(b * TLEN + (t - M_PREFIX)) * D_MODEL + c] = v;
    }
    g_xe[i] = v;
}

// ---------------- lifeline + RoPE; emits f32 residual + bf16 hi/lo ----------------
__global__ void k_prerope(const float* __restrict__ gate, float loop_i) {
    int row = blockIdx.x;
    int j = threadIdx.x;              // pair index 0..1023
    int b = row / TE, t = row % TE;
    float v0 = g_xe[row * D_MODEL + 2*j];
    float v1 = g_xe[row * D_MODEL + 2*j + 1];
    if (t >= M_PREFIX) {
        int pr = (b * TLEN + t - M_PREFIX) * D_MODEL;
        v0 += gate[2*j]     * g_xp[pr + 2*j];
        v1 += gate[2*j + 1] * g_xp[pr + 2*j + 1];
    }
    float freq = loop_i * powf(10000.0f, -(float)(2*j) / (float)D_MODEL);
    float s, c;
    sincosf(freq, &s, &c);
    float r0 = v0 * c - v1 * s;
    float r1 = v1 * c + v0 * s;
    size_t o = (size_t)row * D_MODEL + 2*j;
    g_xe[o] = r0; g_xe[o + 1] = r1;
    split1(r0, g_actH, g_actL, o);
    split1(r1, g_actH, g_actL, o + 1);
}

// ---------------- conv (K=4) + bias + silu, fused with dt/dA ----------------
__global__ void k_conv(const float* __restrict__ cw, const float* __restrict__ cb,
                       const float* __restrict__ dt_bias, const float* __restrict__ A_log) {
    int i = blockIdx.x * 256 + threadIdx.x;
    if (i < ROWS * NHEADS) {
        int row = i / NHEADS, h = i % NHEADS;
        float x = g_zx[(size_t)row * DIN + (2*D_MODEL + 2*D_STATE) + h] + dt_bias[h];
        float sp = (x > 20.f) ? x : log1pf(expf(x));
        g_dt[i] = sp;
        g_dA[i] = expf(-expf(A_log[h]) * sp);
    }
    if (i >= ROWS * CONV_CH) return;
    int row = i / CONV_CH, c = i % CONV_CH;
    int b = row / TE, t = row % TE;
    float acc = cb[c];
#pragma unroll
    for (int k = 0; k < D_CONVK; k++) {
        int tt = t - (D_CONVK - 1) + k;
        if (tt >= 0) acc += g_zx[((size_t)(b*TE + tt)) * DIN + D_MODEL + c] * cw[c*D_CONVK + k];
    }
    g_xbc[i] = siluf(acc);
}

// ---------------- chunked scan phase 1: local scan per (seq, chunk) ----------------
__global__ void k_scan_local(const float* __restrict__ D_skip) {
    int sc = blockIdx.x;               // seq * NCH + c
    int seq = sc / NCH, c = sc % NCH;
    int b = seq >> 4, h = seq & 15;
    int p = threadIdx.x;
    int t0 = c * CHL;
    float hs[D_STATE];
#pragma unroll
    for (int n = 0; n < D_STATE; n++) hs[n] = 0.f;
    __shared__ float sB[2][D_STATE], sC[2][D_STATE];
    float Dh = D_skip[h];
    float cum = 1.f;

    const float* row0 = g_xbc + (size_t)(b*TE + t0) * CONV_CH;
    if (p < 2*D_STATE) {
        float v = row0[D_MODEL + p];
        if (p < D_STATE) sB[0][p] = v; else sC[0][p - D_STATE] = v;
    }
    float x   = row0[h * HEADDIM + p];
    float dAv = g_dA[(size_t)(b*TE + t0) * NHEADS + h];
    float dtv = g_dt[(size_t)(b*TE + t0) * NHEADS + h];
    __syncthreads();

    for (int tt = 0; tt < CHL; tt++) {
        int t = t0 + tt;
        int tn = (tt + 1 < CHL) ? t + 1 : t;
        size_t rn = (size_t)(b*TE + tn);
        const float* rown = g_xbc + rn * CONV_CH;
        float xn   = rown[h * HEADDIM + p];
        float dAn  = g_dA[rn * NHEADS + h];
        float dtn  = g_dt[rn * NHEADS + h];
        int nxt = (tt + 1) & 1, cur = tt & 1;
        if (p < 2*D_STATE) {
            float v = rown[D_MODEL + p];
            if (p < D_STATE) sB[nxt][p] = v; else sC[nxt][p - D_STATE] = v;
        }
        cum *= dAv;
        float coef = dtv * x;
        float a0 = 0.f, a1 = 0.f, a2 = 0.f, a3 = 0.f;
#pragma unroll
        for (int n = 0; n < D_STATE; n += 4) {
            hs[n+0] = dAv * hs[n+0] + coef * sB[cur][n+0]; a0 += hs[n+0] * sC[cur][n+0];
            hs[n+1] = dAv * hs[n+1] + coef * sB[cur][n+1]; a1 += hs[n+1] * sC[cur][n+1];
            hs[n+2] = dAv * hs[n+2] + coef * sB[cur][n+2]; a2 += hs[n+2] * sC[cur][n+2];
            hs[n+3] = dAv * hs[n+3] + coef * sB[cur][n+3]; a3 += hs[n+3] * sC[cur][n+3];
        }
        g_y[(size_t)(b*TE + t) * D_MODEL + h * HEADDIM + p] = (a0 + a1) + (a2 + a3) + Dh * x;
        if (p == 0) g_cum[seq * TE + t] = cum;
        __syncthreads();
        x = xn; dAv = dAn; dtv = dtn;
    }
    size_t hbase = (size_t)sc * (HEADDIM * D_STATE) + (size_t)p * D_STATE;
#pragma unroll
    for (int n = 0; n < D_STATE; n++) g_hs[hbase + n] = hs[n];
    if (p == 0) g_pa[sc] = cum;
}

// ---------------- chunked scan phase 2+3 fused: inline h_start prefix, then fixup ----------------
__global__ void k_scan_fix() {
    int sc = blockIdx.x;
    int seq = sc / NCH, c = sc % NCH;
    if (c == 0) return;                // h_start is zero
    int b = seq >> 4, h = seq & 15;
    int p = threadIdx.x;
    int t0 = c * CHL;
    __shared__ float sC[CHL][D_STATE + 1];
    __shared__ float scum[CHL];
    for (int i = p; i < CHL * D_STATE; i += HEADDIM) {
        int tt = i / D_STATE, n = i % D_STATE;
        sC[tt][n] = g_xbc[(size_t)(b*TE + t0 + tt) * CONV_CH + D_MODEL + D_STATE + n];
    }
    if (p < CHL) scum[p] = g_cum[seq * TE + t0 + p];
    // inline combine: h_start = scan over chunks 0..c-1 of local ends
    float hrow[D_STATE];
#pragma unroll
    for (int n = 0; n < D_STATE; n++) hrow[n] = 0.f;
    for (int c2 = 0; c2 < c; c2++) {
        float pa = g_pa[seq * NCH + c2];
        size_t hb = (size_t)(seq * NCH + c2) * (HEADDIM * D_STATE) + (size_t)p * D_STATE;
#pragma unroll
        for (int n = 0; n < D_STATE; n++)
            hrow[n] = pa * hrow[n] + g_hs[hb + n];
    }
    __syncthreads();
#pragma unroll 4
    for (int tt = 0; tt < CHL; tt++) {
        float d0 = 0.f, d1 = 0.f;
#pragma unroll
        for (int n = 0; n < D_STATE; n += 2) {
            d0 += hrow[n]   * sC[tt][n];
            d1 += hrow[n+1] * sC[tt][n+1];
        }
        size_t yi = (size_t)(b*TE + t0 + tt) * D_MODEL + h * HEADDIM + p;
        g_y[yi] += scum[tt] * (d0 + d1);
    }
}

// ---------------- y * silu(z), rmsnorm -> fp16 (Wout GEMM A) ----------------
__global__ void k_gatenorm(const float* __restrict__ w) {
    int row = blockIdx.x;
    const float* yr = g_y + (size_t)row * D_MODEL;
    const float* zr = g_zx + (size_t)row * DIN;
    float vals[8];
    float ss = 0.f;
#pragma unroll
    for (int q = 0; q < 8; q++) {
        int j = threadIdx.x + q * 256;
        float z = zr[j];
        float v = yr[j] * siluf(z);
        vals[q] = v; ss += v * v;
    }
    __shared__ float sred[8];
    for (int o = 16; o > 0; o >>= 1) ss += __shfl_down_sync(0xffffffffu, ss, o);
    if ((threadIdx.x & 31) == 0) sred[threadIdx.x >> 5] = ss;
    __syncthreads();
    if (threadIdx.x < 8) {
        float t = sred[threadIdx.x];
        t += __shfl_down_sync(0xffu, t, 4);
        t += __shfl_down_sync(0xffu, t, 2);
        t += __shfl_down_sync(0xffu, t, 1);
        if (threadIdx.x == 0) sred[0] = t;
    }
    __syncthreads();
    float scale = rsqrtf(sred[0] / (float)D_MODEL + 1e-6f);
#pragma unroll
    for (int q = 0; q < 8; q++) {
        int j = threadIdx.x + q * 256;
        g_actF[(size_t)row * D_MODEL + j] = __float2half(vals[q] * scale * w[j]);
    }
}

// ---------------- xe = rmsnorm(xe + mamba_out, loop_norm_w) in place ----------------
__global__ void k_addnorm(const float* __restrict__ w) {
    int row = blockIdx.x;
    float vals[8];
    float ss = 0.f;
#pragma unroll
    for (int q = 0; q < 8; q++) {
        int j = threadIdx.x + q * 256;
        float v = g_xe[(size_t)row * D_MODEL + j] + g_mo[(size_t)row * D_MODEL + j];
        vals[q] = v; ss += v * v;
    }
    __shared__ float sred[8];
    for (int o = 16; o > 0; o >>= 1) ss += __shfl_down_sync(0xffffffffu, ss, o);
    if ((threadIdx.x & 31) == 0) sred[threadIdx.x >> 5] = ss;
    __syncthreads();
    if (threadIdx.x < 8) {
        float t = sred[threadIdx.x];
        t += __shfl_down_sync(0xffu, t, 4);
        t += __shfl_down_sync(0xffu, t, 2);
        t += __shfl_down_sync(0xffu, t, 1);
        if (threadIdx.x == 0) sred[0] = t;
    }
    __syncthreads();
    float scale = rsqrtf(sred[0] / (float)D_MODEL + 1e-6f);
#pragma unroll
    for (int q = 0; q < 8; q++) {
        int j = threadIdx.x + q * 256;
        g_xe[(size_t)row * D_MODEL + j] = vals[q] * scale * w[j];
    }
}

// ---------------- bridge down: t1 = xe @ down^T (rank 64) ----------------
__global__ void k_bridge_down(const float* __restrict__ down) {
    int m = blockIdx.x;
    int r = threadIdx.x >> 2;
    int part = threadIdx.x & 3;
    const float* xr = g_xe + (size_t)m * D_MODEL;
    const float* dr = down + r * D_MODEL;
    float acc = 0.f;
    int k0 = part * 512;
    for (int k = k0; k < k0 + 512; k++) acc += xr[k] * dr[k];
    acc += __shfl_down_sync(0xffffffffu, acc, 1);
    acc += __shfl_down_sync(0xffffffffu, acc, 2);
    if (part == 0) g_t1[m * BRIDGE_RANK + r] = acc;
}

// ---------------- bridge up + residual + extract -> fp16 (logits A) ----------------
__global__ void k_bridge_up(const float* __restrict__ up) {
    int ro = blockIdx.x;
    int jc = blockIdx.y;
    int b = ro >> 9, t = M_PREFIX + (ro & 511);
    int m = b * TE + t;
    __shared__ float s1[BRIDGE_RANK];
    if (threadIdx.x < BRIDGE_RANK) s1[threadIdx.x] = g_t1[m * BRIDGE_RANK + threadIdx.x];
    __syncthreads();
    int j = jc * 256 + threadIdx.x;
    float acc = g_xe[(size_t)m * D_MODEL + j];
#pragma unroll
    for (int r = 0; r < BRIDGE_RANK; r++) acc += s1[r] * up[j * BRIDGE_RANK + r];
    g_finF[(size_t)ro * D_MODEL + j] = __float2half(acc);
}

// ---------------- launch ----------------
extern "C" void kernel_launch(void* const* d_in, const int* in_sizes, int n_in,
                              void* d_out, int out_size) {
    const int*   ids         = (const int*)  d_in[0];
    const float* emb         = (const float*)d_in[1];
    const float* latent      = (const float*)d_in[2];
    const float* gate        = (const float*)d_in[3];
    const float* loop_norm_w = (const float*)d_in[4];
    const float* in_base     = (const float*)d_in[5];
    const float* in_A        = (const float*)d_in[6];
    const float* in_B        = (const float*)d_in[7];
    const float* conv_w      = (const float*)d_in[8];
    const float* conv_b      = (const float*)d_in[9];
    const float* dt_bias     = (const float*)d_in[10];
    const float* A_log       = (const float*)d_in[11];
    const float* D_skip      = (const float*)d_in[12];
    const float* ssm_norm_w  = (const float*)d_in[13];
    const float* out_base    = (const float*)d_in[14];
    const float* out_A       = (const float*)d_in[15];
    const float* out_B       = (const float*)d_in[16];
    const float* bridge_down = (const float*)d_in[17];
    const float* bridge_up   = (const float*)d_in[18];
    float* out = (float*)d_out;

    float *pZx, *pMo;
    __nv_bfloat16 *pWinH, *pWinL, *pActH, *pActL;
    __half *pWoutF, *pActF, *pEmbF, *pFinF;
    cudaGetSymbolAddress((void**)&pZx,    g_zx);
    cudaGetSymbolAddress((void**)&pMo,    g_mo);
    cudaGetSymbolAddress((void**)&pWinH,  g_WinH);
    cudaGetSymbolAddress((void**)&pWinL,  g_WinL);
    cudaGetSymbolAddress((void**)&pActH,  g_actH);
    cudaGetSymbolAddress((void**)&pActL,  g_actL);
    cudaGetSymbolAddress((void**)&pWoutF, g_WoutF);
    cudaGetSymbolAddress((void**)&pActF,  g_actF);
    cudaGetSymbolAddress((void**)&pEmbF,  g_embF);
    cudaGetSymbolAddress((void**)&pFinF,  g_finF);

    cudaFuncSetAttribute(gemm_bf3, cudaFuncAttributeMaxDynamicSharedMemorySize, 2 * STG_BF);
    cudaFuncSetAttribute(gemm_f16, cudaFuncAttributeMaxDynamicSharedMemorySize, 2 * STG_F);

    k_lora2<<<((DIN + D_MODEL) * D_MODEL + 255) / 256, 256>>>(
        in_base, in_A, in_B, out_base, out_A, out_B);
    k_embed<<<(ROWS * D_MODEL + 255) / 256, 256>>>(ids, emb, latent);

    for (int li = 0; li < MAX_LOOPS; li++) {
        k_prerope<<<ROWS, 1024>>>(gate, (float)li);
        gemm_bf3<<<dim3((ROWS + 127) / 128, (DIN + 127) / 128), 512, 2 * STG_BF>>>(
            pActH, pActL, pWinH, pWinL, pZx, ROWS, DIN, D_MODEL);
        k_conv<<<(ROWS * CONV_CH + 255) / 256, 256>>>(conv_w, conv_b, dt_bias, A_log);
        k_scan_local<<<NSEQ * NCH, HEADDIM>>>(D_skip);
        k_scan_fix<<<NSEQ * NCH, HEADDIM>>>();
        k_gatenorm<<<ROWS, 256>>>(ssm_norm_w);
        gemm_f16<<<dim3((ROWS + 127) / 128, D_MODEL / 128), 512, 2 * STG_F>>>(
            pActF, pWoutF, pMo, ROWS, D_MODEL, D_MODEL);
        k_addnorm<<<ROWS, 256>>>(loop_norm_w);
    }

    k_bridge_down<<<ROWS, 256>>>(bridge_down);
    k_bridge_up<<<dim3(OUTROWS, D_MODEL / 256), 256>>>(bridge_up);
    {
        size_t n4 = (size_t)VOCAB * D_MODEL / 4;
        k_cvt_f16<<<(unsigned)((n4 + 255) / 256), 256>>>(emb, pEmbF, n4);
    }
    gemm_f16<<<dim3(OUTROWS / 128, VOCAB / 128), 512, 2 * STG_F>>>(
        pFinF, pEmbF, out, OUTROWS, VOCAB, D_MODEL);
}

// round 17
// speedup vs baseline: 1.0540x; 1.0002x over previous
#include <cuda_runtime.h>
#include <cuda_bf16.h>
#include <cuda_fp16.h>
#include <math.h>
#include <stdint.h>

#define D_MODEL 2048
#define D_STATE 32
#define HEADDIM 128
#define NHEADS 16
#define D_CONVK 4
#define M_PREFIX 8
#define MAX_LOOPS 6
#define BRIDGE_RANK 64
#define VOCAB 50432
#define LORA_RANK 4
#define BSZ 2
#define TLEN 512
#define TE (M_PREFIX + TLEN)     /* 520 */
#define ROWS (BSZ * TE)          /* 1040 */
#define DIN (2*D_MODEL + 2*D_STATE + NHEADS)  /* 4176 */
#define CONV_CH (D_MODEL + 2*D_STATE)         /* 2112 */
#define OUTROWS (BSZ * TLEN)     /* 1024 */
#define NSEQ (BSZ * NHEADS)      /* 32 */
#define NCH 13
#define CHL 40                   /* NCH * CHL == TE */

// ---------------- scratch (static device globals; no allocs) ----------------
__device__ float g_xe[ROWS * D_MODEL];
__device__ float g_xp[OUTROWS * D_MODEL];
__device__ float g_zx[ROWS * DIN];
__device__ float g_xbc[ROWS * CONV_CH];
__device__ float g_dt[ROWS * NHEADS];
__device__ float g_dA[ROWS * NHEADS];
__device__ float g_y[ROWS * D_MODEL];
__device__ float g_mo[ROWS * D_MODEL];
__device__ float g_t1[ROWS * BRIDGE_RANK];
// chunked-scan state (g_hs holds per-chunk LOCAL end states)
__device__ float g_hs[(size_t)NSEQ * NCH * HEADDIM * D_STATE];
__device__ float g_pa[NSEQ * NCH];
__device__ float g_cum[NSEQ * TE];

// bf16 hi/lo operand buffers (Win GEMM)
__device__ __nv_bfloat16 g_WinH[DIN * D_MODEL],   g_WinL[DIN * D_MODEL];
__device__ __nv_bfloat16 g_actH[ROWS * D_MODEL],  g_actL[ROWS * D_MODEL];
// fp16 operand buffers (Wout GEMM + logits GEMM, single-pass)
__device__ __half g_WoutF[D_MODEL * D_MODEL];
__device__ __half g_actF[ROWS * D_MODEL];
__device__ __half g_embF[(size_t)VOCAB * D_MODEL];
__device__ __half g_finF[OUTROWS * D_MODEL];

__device__ __forceinline__ float siluf(float x) { return x / (1.0f + expf(-x)); }

__device__ __forceinline__ uint32_t smem_u32(const void* p) {
    uint32_t a;
    asm("{ .reg .u64 t; cvta.to.shared.u64 t, %1; cvt.u32.u64 %0, t; }" : "=r"(a) : "l"(p));
    return a;
}
__device__ __forceinline__ void cpa16(uint32_t dst, const void* src, uint32_t bytes) {
    asm volatile("cp.async.cg.shared.global [%0], [%1], 16, %2;" :: "r"(dst), "l"(src), "r"(bytes));
}
__device__ __forceinline__ void split1(float v, __nv_bfloat16* hi, __nv_bfloat16* lo, size_t i) {
    __nv_bfloat16 h = __float2bfloat16(v);
    hi[i] = h;
    lo[i] = __float2bfloat16(v - __bfloat162float(h));
}

// ================= shared GEMM tile constants =================
#define KC 32
#define SROW 40
#define AB128 (128 * SROW * 2)      /* 10240 bytes per array */
#define STG_BF (4 * AB128)          /* bf3: AH AL BH BL */
#define STG_F  (2 * AB128)          /* f16: A B */

#define LDSM4(r, addr) \
    asm volatile("ldmatrix.sync.aligned.m8n8.x4.shared.b16 {%0,%1,%2,%3}, [%4];" \
        : "=r"((r)[0]), "=r"((r)[1]), "=r"((r)[2]), "=r"((r)[3]) : "r"(addr))

#define MMA_BF(d, a, b0, b1) \
    asm volatile("mma.sync.aligned.m16n8k16.row.col.f32.bf16.bf16.f32 " \
        "{%0,%1,%2,%3},{%4,%5,%6,%7},{%8,%9},{%0,%1,%2,%3};" \
        : "+f"((d)[0]), "+f"((d)[1]), "+f"((d)[2]), "+f"((d)[3]) \
        : "r"((a)[0]), "r"((a)[1]), "r"((a)[2]), "r"((a)[3]), "r"(b0), "r"(b1))

#define MMA_F16(d, a, b0, b1) \
    asm volatile("mma.sync.aligned.m16n8k16.row.col.f32.f16.f16.f32 " \
        "{%0,%1,%2,%3},{%4,%5,%6,%7},{%8,%9},{%0,%1,%2,%3};" \
        : "+f"((d)[0]), "+f"((d)[1]), "+f"((d)[2]), "+f"((d)[3]) \
        : "r"((a)[0]), "r"((a)[1]), "r"((a)[2]), "r"((a)[3]), "r"(b0), "r"(b1))

// ---- epilogue: warp tile 32x32, 4x4 warp grid (both GEMMs, 512 thr) ----
__device__ __forceinline__ void epi_store2(float acc[2][4][4], float* C,
        int m0, int n0, int M, int N, int wm, int wn, int lane) {
#pragma unroll
    for (int mt = 0; mt < 2; mt++) {
#pragma unroll
        for (int nt = 0; nt < 4; nt++) {
            int m = m0 + wm * 32 + mt * 16 + (lane >> 2);
            int n = n0 + wn * 32 + nt * 8 + (lane & 3) * 2;
            if (n < N) {
                if (m < M) {
                    float2 v = make_float2(acc[mt][nt][0], acc[mt][nt][1]);
                    *(float2*)(C + (size_t)m * N + n) = v;
                }
                if (m + 8 < M) {
                    float2 v = make_float2(acc[mt][nt][2], acc[mt][nt][3]);
                    *(float2*)(C + (size_t)(m + 8) * N + n) = v;
                }
            }
        }
    }
}

// ================= bf16x3 GEMM (Win): C = A @ B^T, TM=128, 512 thr =================
__global__ void __launch_bounds__(512, 2) gemm_bf3(
        const __nv_bfloat16* __restrict__ AH, const __nv_bfloat16* __restrict__ AL,
        const __nv_bfloat16* __restrict__ BH, const __nv_bfloat16* __restrict__ BL,
        float* __restrict__ C, int M, int N, int K) {
    extern __shared__ __align__(16) char smdyn[];
    uint32_t sb = smem_u32(smdyn);

    int tid = threadIdx.x, lane = tid & 31, wid = tid >> 5;   // wid 0..15
    int wm = wid >> 2, wn = wid & 3;                          // 4 x 4 warp grid
    int m0 = blockIdx.x * 128, n0 = blockIdx.y * 128;

    float acc[2][4][4] = {};

    const __nv_bfloat16* bases[4] = {AH, AL, BH, BL};
    auto issue_loads = [&](uint32_t stagebase, int k0) {
#pragma unroll
        for (int i = 0; i < 4; i++) {
            int c = tid;                      // chunk within array
            int row = c >> 2, col = c & 3;
            int g = ((i < 2) ? m0 : n0) + row;
            int lim = (i < 2) ? M : N;
            uint32_t bytes = 16;
            if (g >= lim) { g = 0; bytes = 0; }
            cpa16(stagebase + (uint32_t)(i * AB128 + row * 80 + col * 16),
                  bases[i] + (size_t)g * K + k0 + col * 8, bytes);
        }
    };

    uint32_t aRow = (uint32_t)(wm * 32 + (lane & 15));
    uint32_t aColB = (uint32_t)((lane >> 4) * 8) * 2;
    uint32_t bRow = (uint32_t)(wn * 32 + ((lane >> 4) & 1) * 8 + (lane & 7));
    uint32_t bColB = (uint32_t)(((lane >> 3) & 1) * 8) * 2;

    const int nch = K >> 5;
    issue_loads(sb, 0);
    asm volatile("cp.async.commit_group;" ::: "memory");
    for (int ch = 0; ch < nch; ch++) {
        asm volatile("cp.async.wait_group 0;" ::: "memory");
        __syncthreads();
        uint32_t uS = sb + (uint32_t)((ch & 1) * STG_BF);
        if (ch + 1 < nch)
            issue_loads(sb + (uint32_t)(((ch + 1) & 1) * STG_BF), (ch + 1) * KC);
        asm volatile("cp.async.commit_group;" ::: "memory");
        uint32_t uAH = uS, uAL = uS + AB128, uBH = uS + 2*AB128, uBL = uS + 3*AB128;
#pragma unroll
        for (int ks = 0; ks < 2; ks++) {
            uint32_t kcb = (uint32_t)(ks * 16) * 2;
            uint32_t a[2][4], b[2][4];
            // pass 1: Ah * Bh
#pragma unroll
            for (int mt = 0; mt < 2; mt++)
                LDSM4(a[mt], uAH + ((aRow + mt * 16) * SROW) * 2 + kcb + aColB);
#pragma unroll
            for (int bt = 0; bt < 2; bt++)
                LDSM4(b[bt], uBH + ((bRow + bt * 16) * SROW) * 2 + kcb + bColB);
#pragma unroll
            for (int mt = 0; mt < 2; mt++)
#pragma unroll
                for (int nt = 0; nt < 4; nt++)
                    MMA_BF(acc[mt][nt], a[mt], b[nt >> 1][(nt & 1) * 2], b[nt >> 1][(nt & 1) * 2 + 1]);
            // pass 2: Ah * Bl (reuse a)
#pragma unroll
            for (int bt = 0; bt < 2; bt++)
                LDSM4(b[bt], uBL + ((bRow + bt * 16) * SROW) * 2 + kcb + bColB);
#pragma unroll
            for (int mt = 0; mt < 2; mt++)
#pragma unroll
                for (int nt = 0; nt < 4; nt++)
                    MMA_BF(acc[mt][nt], a[mt], b[nt >> 1][(nt & 1) * 2], b[nt >> 1][(nt & 1) * 2 + 1]);
            // pass 3: Al * Bh (reload both)
#pragma unroll
            for (int mt = 0; mt < 2; mt++)
                LDSM4(a[mt], uAL + ((aRow + mt * 16) * SROW) * 2 + kcb + aColB);
#pragma unroll
            for (int bt = 0; bt < 2; bt++)
                LDSM4(b[bt], uBH + ((bRow + bt * 16) * SROW) * 2 + kcb + bColB);
#pragma unroll
            for (int mt = 0; mt < 2; mt++)
#pragma unroll
                for (int nt = 0; nt < 4; nt++)
                    MMA_BF(acc[mt][nt], a[mt], b[nt >> 1][(nt & 1) * 2], b[nt >> 1][(nt & 1) * 2 + 1]);
        }
    }
    epi_store2(acc, C, m0, n0, M, N, wm, wn, lane);
}

// ================= fp16 GEMM (Wout + logits): 512 thr, warp tile 32x32 =================
__global__ void __launch_bounds__(512, 2) gemm_f16(
        const __half* __restrict__ A, const __half* __restrict__ B,
        float* __restrict__ C, int M, int N, int K) {
    extern __shared__ __align__(16) char smdyn[];
    uint32_t sb = smem_u32(smdyn);

    int tid = threadIdx.x, lane = tid & 31, wid = tid >> 5;   // wid 0..15
    int wm = wid >> 2, wn = wid & 3;                          // 4 x 4 warp grid
    int m0 = blockIdx.x * 128, n0 = blockIdx.y * 128;

    float acc[2][4][4] = {};

    uint32_t aRow = (uint32_t)(wm * 32 + (lane & 15));
    uint32_t aColB = (uint32_t)((lane >> 4) * 8) * 2;
    uint32_t bRow = (uint32_t)(wn * 32 + ((lane >> 4) & 1) * 8 + (lane & 7));
    uint32_t bColB = (uint32_t)(((lane >> 3) & 1) * 8) * 2;

    const int nch = K >> 5;
    auto issue_loads = [&](uint32_t stagebase, int k0) {
#pragma unroll
        for (int i = 0; i < 2; i++) {
            int c = tid;
            int row = c >> 2, col = c & 3;
            const __half* base = (i == 0) ? A : B;
            int g = ((i == 0) ? m0 : n0) + row;
            int lim = (i == 0) ? M : N;
            uint32_t bytes = 16;
            if (g >= lim) { g = 0; bytes = 0; }
            cpa16(stagebase + (uint32_t)(i * AB128 + row * 80 + col * 16),
                  base + (size_t)g * K + k0 + col * 8, bytes);
        }
    };

    issue_loads(sb, 0);
    asm volatile("cp.async.commit_group;" ::: "memory");
    for (int ch = 0; ch < nch; ch++) {
        asm volatile("cp.async.wait_group 0;" ::: "memory");
        __syncthreads();
        uint32_t uS = sb + (uint32_t)((ch & 1) * STG_F);
        if (ch + 1 < nch)
            issue_loads(sb + (uint32_t)(((ch + 1) & 1) * STG_F), (ch + 1) * KC);
        asm volatile("cp.async.commit_group;" ::: "memory");
        uint32_t uA = uS, uB = uS + AB128;
#pragma unroll
        for (int ks = 0; ks < 2; ks++) {
            uint32_t kcb = (uint32_t)(ks * 16) * 2;
            uint32_t a[2][4], b[2][4];
#pragma unroll
            for (int mt = 0; mt < 2; mt++)
                LDSM4(a[mt], uA + ((aRow + mt * 16) * SROW) * 2 + kcb + aColB);
#pragma unroll
            for (int bt = 0; bt < 2; bt++)
                LDSM4(b[bt], uB + ((bRow + bt * 16) * SROW) * 2 + kcb + bColB);
#pragma unroll
            for (int mt = 0; mt < 2; mt++)
#pragma unroll
                for (int nt = 0; nt < 4; nt++)
                    MMA_F16(acc[mt][nt], a[mt], b[nt >> 1][(nt & 1) * 2], b[nt >> 1][(nt & 1) * 2 + 1]);
        }
    }
    epi_store2(acc, C, m0, n0, M, N, wm, wn, lane);
}

// ---------------- fused LoRA fold: Win -> bf16 hi/lo, Wout -> fp16 ----------------
__global__ void k_lora2(const float* __restrict__ in_base, const float* __restrict__ in_A,
                        const float* __restrict__ in_B,
                        const float* __restrict__ out_base, const float* __restrict__ out_A,
                        const float* __restrict__ out_B) {
    int i = blockIdx.x * 256 + threadIdx.x;
    const int T1 = DIN * D_MODEL;
    if (i < T1) {
        int r = i / D_MODEL, c = i % D_MODEL;
        float s = 0.f;
#pragma unroll
        for (int q = 0; q < LORA_RANK; q++) s += in_B[r*LORA_RANK + q] * in_A[q*D_MODEL + c];
        split1(in_base[i] + 2.0f * s, g_WinH, g_WinL, i);
    } else {
        int j = i - T1;
        if (j >= D_MODEL * D_MODEL) return;
        int r = j / D_MODEL, c = j % D_MODEL;
        float s = 0.f;
#pragma unroll
        for (int q = 0; q < LORA_RANK; q++) s += out_B[r*LORA_RANK + q] * out_A[q*D_MODEL + c];
        g_WoutF[j] = __float2half(out_base[j] + 2.0f * s);
    }
}

// ---------------- f32 -> fp16 convert (vectorized), for emb ----------------
__global__ void k_cvt_f16(const float* __restrict__ in, __half* __restrict__ o, size_t n4) {
    size_t i = (size_t)blockIdx.x * 256 + threadIdx.x;
    if (i >= n4) return;
    float4 v = *(const float4*)(in + i * 4);
    __half2 p0 = __floats2half2_rn(v.x, v.y);
    __half2 p1 = __floats2half2_rn(v.z, v.w);
    uint2 pk;
    pk.x = *(uint32_t*)&p0;
    pk.y = *(uint32_t*)&p1;
    *(uint2*)(o + i * 4) = pk;
}

// ---------------- embedding gather + latent prefix ----------------
__global__ void k_embed(const int* __restrict__ ids, const float* __restrict__ emb,
                        const float* __restrict__ latent) {
    int i = blockIdx.x * 256 + threadIdx.x;
    if (i >= ROWS * D_MODEL) return;
    int row = i / D_MODEL, c = i % D_MODEL;
    int b = row / TE, t = row % TE;
    float v;
    if (t < M_PREFIX) {
        v = latent[t * D_MODEL + c];
    } else {
        int tok = ids[b * TLEN + (t - M_PREFIX)];
        v = emb[(size_t)tok * D_MODEL + c];
        g_xp[(b * TLEN + (t - M_PREFIX)) * D_MODEL + c] = v;
    }
    g_xe[i] = v;
}

// ---------------- lifeline + RoPE; emits f32 residual + bf16 hi/lo ----------------
__global__ void k_prerope(const float* __restrict__ gate, float loop_i) {
    int row = blockIdx.x;
    int j = threadIdx.x;              // pair index 0..1023
    int b = row / TE, t = row % TE;
    float v0 = g_xe[row * D_MODEL + 2*j];
    float v1 = g_xe[row * D_MODEL + 2*j + 1];
    if (t >= M_PREFIX) {
        int pr = (b * TLEN + t - M_PREFIX) * D_MODEL;
        v0 += gate[2*j]     * g_xp[pr + 2*j];
        v1 += gate[2*j + 1] * g_xp[pr + 2*j + 1];
    }
    float freq = loop_i * powf(10000.0f, -(float)(2*j) / (float)D_MODEL);
    float s, c;
    sincosf(freq, &s, &c);
    float r0 = v0 * c - v1 * s;
    float r1 = v1 * c + v0 * s;
    size_t o = (size_t)row * D_MODEL + 2*j;
    g_xe[o] = r0; g_xe[o + 1] = r1;
    split1(r0, g_actH, g_actL, o);
    split1(r1, g_actH, g_actL, o + 1);
}

// ---------------- conv (K=4) + bias + silu, fused with dt/dA ----------------
__global__ void k_conv(const float* __restrict__ cw, const float* __restrict__ cb,
                       const float* __restrict__ dt_bias, const float* __restrict__ A_log) {
    int i = blockIdx.x * 256 + threadIdx.x;
    if (i < ROWS * NHEADS) {
        int row = i / NHEADS, h = i % NHEADS;
        float x = g_zx[(size_t)row * DIN + (2*D_MODEL + 2*D_STATE) + h] + dt_bias[h];
        float sp = (x > 20.f) ? x : log1pf(expf(x));
        g_dt[i] = sp;
        g_dA[i] = expf(-expf(A_log[h]) * sp);
    }
    if (i >= ROWS * CONV_CH) return;
    int row = i / CONV_CH, c = i % CONV_CH;
    int b = row / TE, t = row % TE;
    float acc = cb[c];
#pragma unroll
    for (int k = 0; k < D_CONVK; k++) {
        int tt = t - (D_CONVK - 1) + k;
        if (tt >= 0) acc += g_zx[((size_t)(b*TE + tt)) * DIN + D_MODEL + c] * cw[c*D_CONVK + k];
    }
    g_xbc[i] = siluf(acc);
}

// ---------------- chunked scan phase 1: local scan per (seq, chunk) ----------------
__global__ void k_scan_local(const float* __restrict__ D_skip) {
    int sc = blockIdx.x;               // seq * NCH + c
    int seq = sc / NCH, c = sc % NCH;
    int b = seq >> 4, h = seq & 15;
    int p = threadIdx.x;
    int t0 = c * CHL;
    float hs[D_STATE];
#pragma unroll
    for (int n = 0; n < D_STATE; n++) hs[n] = 0.f;
    __shared__ float sB[2][D_STATE], sC[2][D_STATE];
    float Dh = D_skip[h];
    float cum = 1.f;

    const float* row0 = g_xbc + (size_t)(b*TE + t0) * CONV_CH;
    if (p < 2*D_STATE) {
        float v = row0[D_MODEL + p];
        if (p < D_STATE) sB[0][p] = v; else sC[0][p - D_STATE] = v;
    }
    float x   = row0[h * HEADDIM + p];
    float dAv = g_dA[(size_t)(b*TE + t0) * NHEADS + h];
    float dtv = g_dt[(size_t)(b*TE + t0) * NHEADS + h];
    __syncthreads();

    for (int tt = 0; tt < CHL; tt++) {
        int t = t0 + tt;
        int tn = (tt + 1 < CHL) ? t + 1 : t;
        size_t rn = (size_t)(b*TE + tn);
        const float* rown = g_xbc + rn * CONV_CH;
        float xn   = rown[h * HEADDIM + p];
        float dAn  = g_dA[rn * NHEADS + h];
        float dtn  = g_dt[rn * NHEADS + h];
        int nxt = (tt + 1) & 1, cur = tt & 1;
        if (p < 2*D_STATE) {
            float v = rown[D_MODEL + p];
            if (p < D_STATE) sB[nxt][p] = v; else sC[nxt][p - D_STATE] = v;
        }
        cum *= dAv;
        float coef = dtv * x;
        float a0 = 0.f, a1 = 0.f, a2 = 0.f, a3 = 0.f;
#pragma unroll
        for (int n = 0; n < D_STATE; n += 4) {
            hs[n+0] = dAv * hs[n+0] + coef * sB[cur][n+0]; a0 += hs[n+0] * sC[cur][n+0];
            hs[n+1] = dAv * hs[n+1] + coef * sB[cur][n+1]; a1 += hs[n+1] * sC[cur][n+1];
            hs[n+2] = dAv * hs[n+2] + coef * sB[cur][n+2]; a2 += hs[n+2] * sC[cur][n+2];
            hs[n+3] = dAv * hs[n+3] + coef * sB[cur][n+3]; a3 += hs[n+3] * sC[cur][n+3];
        }
        g_y[(size_t)(b*TE + t) * D_MODEL + h * HEADDIM + p] = (a0 + a1) + (a2 + a3) + Dh * x;
        if (p == 0) g_cum[seq * TE + t] = cum;
        __syncthreads();
        x = xn; dAv = dAn; dtv = dtn;
    }
    size_t hbase = (size_t)sc * (HEADDIM * D_STATE) + (size_t)p * D_STATE;
#pragma unroll
    for (int n = 0; n < D_STATE; n++) g_hs[hbase + n] = hs[n];
    if (p == 0) g_pa[sc] = cum;
}

// ---------------- chunked scan phase 2+3 fused: inline h_start prefix, then fixup ----------------
__global__ void k_scan_fix() {
    int sc = blockIdx.x;
    int seq = sc / NCH, c = sc % NCH;
    if (c == 0) return;                // h_start is zero
    int b = seq >> 4, h = seq & 15;
    int p = threadIdx.x;
    int t0 = c * CHL;
    __shared__ float sC[CHL][D_STATE + 1];
    __shared__ float scum[CHL];
    for (int i = p; i < CHL * D_STATE; i += HEADDIM) {
        int tt = i / D_STATE, n = i % D_STATE;
        sC[tt][n] = g_xbc[(size_t)(b*TE + t0 + tt) * CONV_CH + D_MODEL + D_STATE + n];
    }
    if (p < CHL) scum[p] = g_cum[seq * TE + t0 + p];
    float hrow[D_STATE];
#pragma unroll
    for (int n = 0; n < D_STATE; n++) hrow[n] = 0.f;
    for (int c2 = 0; c2 < c; c2++) {
        float pa = g_pa[seq * NCH + c2];
        size_t hb = (size_t)(seq * NCH + c2) * (HEADDIM * D_STATE) + (size_t)p * D_STATE;
#pragma unroll
        for (int n = 0; n < D_STATE; n++)
            hrow[n] = pa * hrow[n] + g_hs[hb + n];
    }
    __syncthreads();
#pragma unroll 4
    for (int tt = 0; tt < CHL; tt++) {
        float d0 = 0.f, d1 = 0.f;
#pragma unroll
        for (int n = 0; n < D_STATE; n += 2) {
            d0 += hrow[n]   * sC[tt][n];
            d1 += hrow[n+1] * sC[tt][n+1];
        }
        size_t yi = (size_t)(b*TE + t0 + tt) * D_MODEL + h * HEADDIM + p;
        g_y[yi] += scum[tt] * (d0 + d1);
    }
}

// ---------------- y * silu(z), rmsnorm -> fp16 (Wout GEMM A) ----------------
__global__ void k_gatenorm(const float* __restrict__ w) {
    int row = blockIdx.x;
    const float* yr = g_y + (size_t)row * D_MODEL;
    const float* zr = g_zx + (size_t)row * DIN;
    float vals[8];
    float ss = 0.f;
#pragma unroll
    for (int q = 0; q < 8; q++) {
        int j = threadIdx.x + q * 256;
        float z = zr[j];
        float v = yr[j] * siluf(z);
        vals[q] = v; ss += v * v;
    }
    __shared__ float sred[8];
    for (int o = 16; o > 0; o >>= 1) ss += __shfl_down_sync(0xffffffffu, ss, o);
    if ((threadIdx.x & 31) == 0) sred[threadIdx.x >> 5] = ss;
    __syncthreads();
    if (threadIdx.x < 8) {
        float t = sred[threadIdx.x];
        t += __shfl_down_sync(0xffu, t, 4);
        t += __shfl_down_sync(0xffu, t, 2);
        t += __shfl_down_sync(0xffu, t, 1);
        if (threadIdx.x == 0) sred[0] = t;
    }
    __syncthreads();
    float scale = rsqrtf(sred[0] / (float)D_MODEL + 1e-6f);
#pragma unroll
    for (int q = 0; q < 8; q++) {
        int j = threadIdx.x + q * 256;
        g_actF[(size_t)row * D_MODEL + j] = __float2half(vals[q] * scale * w[j]);
    }
}

// ---------------- xe = rmsnorm(xe + mamba_out, loop_norm_w) in place ----------------
__global__ void k_addnorm(const float* __restrict__ w) {
    int row = blockIdx.x;
    float vals[8];
    float ss = 0.f;
#pragma unroll
    for (int q = 0; q < 8; q++) {
        int j = threadIdx.x + q * 256;
        float v = g_xe[(size_t)row * D_MODEL + j] + g_mo[(size_t)row * D_MODEL + j];
        vals[q] = v; ss += v * v;
    }
    __shared__ float sred[8];
    for (int o = 16; o > 0; o >>= 1) ss += __shfl_down_sync(0xffffffffu, ss, o);
    if ((threadIdx.x & 31) == 0) sred[threadIdx.x >> 5] = ss;
    __syncthreads();
    if (threadIdx.x < 8) {
        float t = sred[threadIdx.x];
        t += __shfl_down_sync(0xffu, t, 4);
        t += __shfl_down_sync(0xffu, t, 2);
        t += __shfl_down_sync(0xffu, t, 1);
        if (threadIdx.x == 0) sred[0] = t;
    }
    __syncthreads();
    float scale = rsqrtf(sred[0] / (float)D_MODEL + 1e-6f);
#pragma unroll
    for (int q = 0; q < 8; q++) {
        int j = threadIdx.x + q * 256;
        g_xe[(size_t)row * D_MODEL + j] = vals[q] * scale * w[j];
    }
}

// ---------------- bridge down: t1 = xe @ down^T (rank 64) ----------------
__global__ void k_bridge_down(const float* __restrict__ down) {
    int m = blockIdx.x;
    int r = threadIdx.x >> 2;
    int part = threadIdx.x & 3;
    const float* xr = g_xe + (size_t)m * D_MODEL;
    const float* dr = down + r * D_MODEL;
    float acc = 0.f;
    int k0 = part * 512;
    for (int k = k0; k < k0 + 512; k++) acc += xr[k] * dr[k];
    acc += __shfl_down_sync(0xffffffffu, acc, 1);
    acc += __shfl_down_sync(0xffffffffu, acc, 2);
    if (part == 0) g_t1[m * BRIDGE_RANK + r] = acc;
}

// ---------------- bridge up + residual + extract -> fp16 (logits A) ----------------
__global__ void k_bridge_up(const float* __restrict__ up) {
    int ro = blockIdx.x;
    int jc = blockIdx.y;
    int b = ro >> 9, t = M_PREFIX + (ro & 511);
    int m = b * TE + t;
    __shared__ float s1[BRIDGE_RANK];
    if (threadIdx.x < BRIDGE_RANK) s1[threadIdx.x] = g_t1[m * BRIDGE_RANK + threadIdx.x];
    __syncthreads();
    int j = jc * 256 + threadIdx.x;
    float acc = g_xe[(size_t)m * D_MODEL + j];
#pragma unroll
    for (int r = 0; r < BRIDGE_RANK; r++) acc += s1[r] * up[j * BRIDGE_RANK + r];
    g_finF[(size_t)ro * D_MODEL + j] = __float2half(acc);
}

// ---------------- launch ----------------
extern "C" void kernel_launch(void* const* d_in, const int* in_sizes, int n_in,
                              void* d_out, int out_size) {
    const int*   ids         = (const int*)  d_in[0];
    const float* emb         = (const float*)d_in[1];
    const float* latent      = (const float*)d_in[2];
    const float* gate        = (const float*)d_in[3];
    const float* loop_norm_w = (const float*)d_in[4];
    const float* in_base     = (const float*)d_in[5];
    const float* in_A        = (const float*)d_in[6];
    const float* in_B        = (const float*)d_in[7];
    const float* conv_w      = (const float*)d_in[8];
    const float* conv_b      = (const float*)d_in[9];
    const float* dt_bias     = (const float*)d_in[10];
    const float* A_log       = (const float*)d_in[11];
    const float* D_skip      = (const float*)d_in[12];
    const float* ssm_norm_w  = (const float*)d_in[13];
    const float* out_base    = (const float*)d_in[14];
    const float* out_A       = (const float*)d_in[15];
    const float* out_B       = (const float*)d_in[16];
    const float* bridge_down = (const float*)d_in[17];
    const float* bridge_up   = (const float*)d_in[18];
    float* out = (float*)d_out;

    float *pZx, *pMo;
    __nv_bfloat16 *pWinH, *pWinL, *pActH, *pActL;
    __half *pWoutF, *pActF, *pEmbF, *pFinF;
    cudaGetSymbolAddress((void**)&pZx,    g_zx);
    cudaGetSymbolAddress((void**)&pMo,    g_mo);
    cudaGetSymbolAddress((void**)&pWinH,  g_WinH);
    cudaGetSymbolAddress((void**)&pWinL,  g_WinL);
    cudaGetSymbolAddress((void**)&pActH,  g_actH);
    cudaGetSymbolAddress((void**)&pActL,  g_actL);
    cudaGetSymbolAddress((void**)&pWoutF, g_WoutF);
    cudaGetSymbolAddress((void**)&pActF,  g_actF);
    cudaGetSymbolAddress((void**)&pEmbF,  g_embF);
    cudaGetSymbolAddress((void**)&pFinF,  g_finF);

    cudaFuncSetAttribute(gemm_bf3, cudaFuncAttributeMaxDynamicSharedMemorySize, 2 * STG_BF);
    cudaFuncSetAttribute(gemm_f16, cudaFuncAttributeMaxDynamicSharedMemorySize, 2 * STG_F);

    // side stream + events for overlapping the emb->fp16 conversion with the loop
    static cudaStream_t s2 = nullptr;
    static cudaEvent_t evFork = nullptr, evJoin = nullptr;
    if (s2 == nullptr) {
        cudaStreamCreateWithFlags(&s2, cudaStreamNonBlocking);
        cudaEventCreateWithFlags(&evFork, cudaEventDisableTiming);
        cudaEventCreateWithFlags(&evJoin, cudaEventDisableTiming);
    }

    // fork: emb f32->f16 conversion runs on side stream, overlapped with the whole loop
    cudaEventRecord(evFork, 0);
    cudaStreamWaitEvent(s2, evFork, 0);
    {
        size_t n4 = (size_t)VOCAB * D_MODEL / 4;
        k_cvt_f16<<<(unsigned)((n4 + 255) / 256), 256, 0, s2>>>(emb, pEmbF, n4);
    }
    cudaEventRecord(evJoin, s2);

    k_lora2<<<((DIN + D_MODEL) * D_MODEL + 255) / 256, 256>>>(
        in_base, in_A, in_B, out_base, out_A, out_B);
    k_embed<<<(ROWS * D_MODEL + 255) / 256, 256>>>(ids, emb, latent);

    for (int li = 0; li < MAX_LOOPS; li++) {
        k_prerope<<<ROWS, 1024>>>(gate, (float)li);
        gemm_bf3<<<dim3((ROWS + 127) / 128, (DIN + 127) / 128), 512, 2 * STG_BF>>>(
            pActH, pActL, pWinH, pWinL, pZx, ROWS, DIN, D_MODEL);
        k_conv<<<(ROWS * CONV_CH + 255) / 256, 256>>>(conv_w, conv_b, dt_bias, A_log);
        k_scan_local<<<NSEQ * NCH, HEADDIM>>>(D_skip);
        k_scan_fix<<<NSEQ * NCH, HEADDIM>>>();
        k_gatenorm<<<ROWS, 256>>>(ssm_norm_w);
        gemm_f16<<<dim3((ROWS + 127) / 128, D_MODEL / 128), 512, 2 * STG_F>>>(
            pActF, pWoutF, pMo, ROWS, D_MODEL, D_MODEL);
        k_addnorm<<<ROWS, 256>>>(loop_norm_w);
    }

    k_bridge_down<<<ROWS, 256>>>(bridge_down);
    k_bridge_up<<<dim3(OUTROWS, D_MODEL / 256), 256>>>(bridge_up);

    // join: logits GEMM needs the converted emb
    cudaStreamWaitEvent(0, evJoin, 0);
    gemm_f16<<<dim3(OUTROWS / 128, VOCAB / 128), 512, 2 * STG_F>>>(
        pFinF, pEmbF, out, OUTROWS, VOCAB, D_MODEL);
}